// round 6
// baseline (speedup 1.0000x reference)
#include <cuda_runtime.h>
#include <math.h>

#define Bsz 128
#define Tsz 1024
#define Fsz 128
#define Hsz 256
#define KC  32
#define NTHR 128
#define TLAST 1020

// Persistent state
__device__ float g_h[3][2][Bsz][Hsz];   // double-buffered hidden state per layer
__device__ float g_c[3][Bsz][Hsz];      // cell state
__device__ unsigned g_cnt[8][32];       // per-group barrier counters (128B padded)
__device__ volatile unsigned g_gen[8][32];

struct SmemT {
    float w[2][KC][4][16];   // [buf][k][gate][j]   8KB x2
    float in[2][KC][16];     // [buf][k][b]         2KB x2
};

__device__ __forceinline__ float sigmoidf_(float x) { return 1.f / (1.f + expf(-x)); }

// 16-block group barrier (blocks sharing one batch slice)
__device__ __forceinline__ void group_sync(int bg, unsigned &gen) {
    __syncthreads();
    if (threadIdx.x == 0) {
        gen++;
        __threadfence();   // drain this CTA's stores to L2 before arriving
        unsigned old = atomicAdd(&g_cnt[bg][0], 1u);
        if (old == 15u) {
            g_cnt[bg][0] = 0u;
            __threadfence();
            atomicExch((unsigned*)&g_gen[bg][0], gen);
        } else {
            while (g_gen[bg][0] != gen) { }
        }
        __threadfence();   // acquire: invalidate L1 so post-barrier reads are fresh
    }
    __syncthreads();
}

__device__ __forceinline__ void store_w(SmemT* s, int buf, int wh, int wg, int wj,
                                        const float4* wv) {
#pragma unroll
    for (int q = 0; q < 4; q++) {
        s->w[buf][wh + q*4 + 0][wg][wj] = wv[q].x;
        s->w[buf][wh + q*4 + 1][wg][wj] = wv[q].y;
        s->w[buf][wh + q*4 + 2][wg][wj] = wv[q].z;
        s->w[buf][wh + q*4 + 3][wg][wj] = wv[q].w;
    }
}

// One GEMM segment: acc += inp[b, :K] * W[n, :K]^T, streamed in KC chunks,
// double-buffered through smem. Thread k-splits 4 ways (ks = tid&3).
__device__ __forceinline__ void do_segment(SmemT* s,
    const float* __restrict__ W, int K,
    const float* __restrict__ inp, long strideB,
    int jbase, int bbase, int ks, int bq, int jp,
    float acc[2][4][4])
{
    const int tid = threadIdx.x;
    const int wg = tid >> 5;            // gate 0..3
    const int wj = (tid >> 1) & 15;     // j within tile
    const int wh = (tid & 1) << 4;      // k half offset 0/16
    const int sb = tid >> 3;            // batch row for input staging
    const int sq = tid & 7;             // k quad for input staging
    const float* wrow = W + (size_t)(wg * Hsz + jbase + wj) * K + wh;
    const float* irow = inp + (size_t)(bbase + sb) * strideB + sq * 4;
    const int nchunk = K / KC;          // 4, 8 — always even

    float4 wv[4]; float4 iv;
#pragma unroll
    for (int q = 0; q < 4; q++) wv[q] = __ldcg((const float4*)(wrow + q*4));
    iv = __ldcg((const float4*)irow);
    store_w(s, 0, wh, wg, wj, wv);
    s->in[0][sq*4+0][sb] = iv.x;
    s->in[0][sq*4+1][sb] = iv.y;
    s->in[0][sq*4+2][sb] = iv.z;
    s->in[0][sq*4+3][sb] = iv.w;
    __syncthreads();

    for (int ci = 0; ci < nchunk; ci++) {
        const int cur = ci & 1;
        const int nxt = cur ^ 1;
        const bool more = (ci + 1 < nchunk);
        if (more) {
            const int k0 = (ci + 1) * KC;
#pragma unroll
            for (int q = 0; q < 4; q++) wv[q] = __ldcg((const float4*)(wrow + k0 + q*4));
            iv = __ldcg((const float4*)(irow + k0));
        }
#pragma unroll
        for (int k8 = 0; k8 < 8; k8++) {
            const int k = k8*4 + ks;
            const float4 xv = *(const float4*)&s->in[cur][k][bq*4];
#pragma unroll
            for (int g = 0; g < 4; g++) {
                const float2 ww = *(const float2*)&s->w[cur][k][g][jp*2];
                acc[0][g][0] = fmaf(ww.x, xv.x, acc[0][g][0]);
                acc[0][g][1] = fmaf(ww.x, xv.y, acc[0][g][1]);
                acc[0][g][2] = fmaf(ww.x, xv.z, acc[0][g][2]);
                acc[0][g][3] = fmaf(ww.x, xv.w, acc[0][g][3]);
                acc[1][g][0] = fmaf(ww.y, xv.x, acc[1][g][0]);
                acc[1][g][1] = fmaf(ww.y, xv.y, acc[1][g][1]);
                acc[1][g][2] = fmaf(ww.y, xv.z, acc[1][g][2]);
                acc[1][g][3] = fmaf(ww.y, xv.w, acc[1][g][3]);
            }
        }
        if (more) {
            // buf[nxt] last read before previous iteration's __syncthreads
            store_w(s, nxt, wh, wg, wj, wv);
            s->in[nxt][sq*4+0][sb] = iv.x;
            s->in[nxt][sq*4+1][sb] = iv.y;
            s->in[nxt][sq*4+2][sb] = iv.z;
            s->in[nxt][sq*4+3][sb] = iv.w;
        }
        __syncthreads();
    }
}

__device__ __forceinline__ void layer_update(SmemT* s,
    const float* __restrict__ WA, int KA, const float* __restrict__ inpA, long strideA,
    const float* __restrict__ WB, const float* __restrict__ inpB,
    const float* __restrict__ bih, const float* __restrict__ bhh,
    float* __restrict__ cbase, float* __restrict__ hout,
    float* __restrict__ yout, int t0,
    int jbase, int bbase)
{
    const int tid = threadIdx.x;
    const int ks  = tid & 3;        // k-split lane
    const int pos = tid >> 2;
    const int bq  = pos & 3;        // batch quad
    const int jp  = pos >> 2;       // j pair

    float acc[2][4][4];
#pragma unroll
    for (int p = 0; p < 2; p++)
#pragma unroll
        for (int g = 0; g < 4; g++)
#pragma unroll
            for (int u = 0; u < 4; u++) acc[p][g][u] = 0.f;

    do_segment(s, WA, KA,  inpA, strideA, jbase, bbase, ks, bq, jp, acc);
    do_segment(s, WB, Hsz, inpB, Hsz,     jbase, bbase, ks, bq, jp, acc);

    // reduce the 4-way k-split across adjacent lanes (ks = lane&3)
#pragma unroll
    for (int p = 0; p < 2; p++)
#pragma unroll
        for (int g = 0; g < 4; g++)
#pragma unroll
            for (int u = 0; u < 4; u++) {
                float v = acc[p][g][u];
                v += __shfl_xor_sync(0xffffffffu, v, 1);
                v += __shfl_xor_sync(0xffffffffu, v, 2);
                acc[p][g][u] = v;
            }

    // each lane handles batch u == ks; select with SELs (no dynamic reg indexing)
    const int j0 = jbase + jp * 2;
    const int b  = bbase + bq * 4 + ks;
#pragma unroll
    for (int p = 0; p < 2; p++) {
        float gv[4];
#pragma unroll
        for (int g = 0; g < 4; g++) {
            float v = acc[p][g][0];
            if (ks == 1) v = acc[p][g][1];
            if (ks == 2) v = acc[p][g][2];
            if (ks == 3) v = acc[p][g][3];
            gv[g] = v;
        }
        const int j = j0 + p;
        const float gi = gv[0] + bih[j]           + bhh[j];
        const float gf = gv[1] + bih[Hsz + j]     + bhh[Hsz + j];
        const float gg = gv[2] + bih[2*Hsz + j]   + bhh[2*Hsz + j];
        const float go = gv[3] + bih[3*Hsz + j]   + bhh[3*Hsz + j];
        const float i_ = sigmoidf_(gi);
        const float f_ = sigmoidf_(gf);
        const float g_ = tanhf(gg);
        const float o_ = sigmoidf_(go);
        const float cn = f_ * cbase[b*Hsz + j] + i_ * g_;
        const float hn = o_ * tanhf(cn);
        cbase[b*Hsz + j] = cn;
        hout[b*Hsz + j]  = hn;
        if (yout) {
#pragma unroll
            for (int u = 0; u < 4; u++)
                yout[((size_t)b * Tsz + (t0 + u)) * Hsz + j] = hn;
        }
    }
}

__global__ void __launch_bounds__(NTHR, 1) drnn_persistent(
    const float* __restrict__ x,
    const float* __restrict__ Wih0, const float* __restrict__ Whh0,
    const float* __restrict__ bih0, const float* __restrict__ bhh0,
    const float* __restrict__ Wih1, const float* __restrict__ Whh1,
    const float* __restrict__ bih1, const float* __restrict__ bhh1,
    const float* __restrict__ Wih2, const float* __restrict__ Whh2,
    const float* __restrict__ bih2, const float* __restrict__ bhh2,
    float* __restrict__ y)
{
    __shared__ SmemT s;
    const int bid = blockIdx.x;
    const int jg = bid & 15;       // 16 j-slices
    const int bg = bid >> 4;       // 8 independent batch groups
    const int jbase = jg * 16;
    const int bbase = bg * 16;
    const int tid = threadIdx.x;

    unsigned gen = 0;
    if (jg == 0 && tid == 0) g_gen[bg][0] = 0;   // reset before first arrive (fenced in sync)

    // zero this block's state slices (covers everything across the group)
    for (int i = tid; i < 256; i += NTHR) {
        const int jj = jbase + (i & 15);
        const int bb = bbase + (i >> 4);
#pragma unroll
        for (int l = 0; l < 3; l++) {
            g_h[l][0][bb][jj] = 0.f;
            g_h[l][1][bb][jj] = 0.f;
            g_c[l][bb][jj]    = 0.f;
        }
    }
    group_sync(bg, gen);

    int p0 = 0, p1 = 0, p2 = 0;
    for (int t = 0; t <= TLAST; t++) {
        // layer 0 — every step
        layer_update(&s, Wih0, Fsz, x + (size_t)t * Fsz, (long)Tsz * Fsz,
                     Whh0, &g_h[0][p0][0][0], bih0, bhh0,
                     &g_c[0][0][0], &g_h[0][p0 ^ 1][0][0], nullptr, 0,
                     jbase, bbase);
        p0 ^= 1;
        group_sync(bg, gen);

        if ((t & 1) == 0) {
            // layer 1 — every 2nd step; reads h0 just written
            layer_update(&s, Wih1, Hsz, &g_h[0][p0][0][0], Hsz,
                         Whh1, &g_h[1][p1][0][0], bih1, bhh1,
                         &g_c[1][0][0], &g_h[1][p1 ^ 1][0][0], nullptr, 0,
                         jbase, bbase);
            p1 ^= 1;
            if ((t & 3) == 0) {
                group_sync(bg, gen);   // layer2 consumes h1 immediately
                layer_update(&s, Wih2, Hsz, &g_h[1][p1][0][0], Hsz,
                             Whh2, &g_h[2][p2][0][0], bih2, bhh2,
                             &g_c[2][0][0], &g_h[2][p2 ^ 1][0][0], y, t,
                             jbase, bbase);
                p2 ^= 1;
            }
            // no barrier needed here: next consumers are separated by the
            // barrier after the following layer-0 update
        }
    }
}

extern "C" void kernel_launch(void* const* d_in, const int* in_sizes, int n_in,
                              void* d_out, int out_size) {
    const float* x    = (const float*)d_in[0];
    const float* Wih0 = (const float*)d_in[1];
    const float* Whh0 = (const float*)d_in[2];
    const float* bih0 = (const float*)d_in[3];
    const float* bhh0 = (const float*)d_in[4];
    const float* Wih1 = (const float*)d_in[5];
    const float* Whh1 = (const float*)d_in[6];
    const float* bih1 = (const float*)d_in[7];
    const float* bhh1 = (const float*)d_in[8];
    const float* Wih2 = (const float*)d_in[9];
    const float* Whh2 = (const float*)d_in[10];
    const float* bih2 = (const float*)d_in[11];
    const float* bhh2 = (const float*)d_in[12];
    float* y = (float*)d_out;

    drnn_persistent<<<128, NTHR>>>(x,
        Wih0, Whh0, bih0, bhh0,
        Wih1, Whh1, bih1, bhh1,
        Wih2, Whh2, bih2, bhh2, y);
}

// round 7
// speedup vs baseline: 1.4584x; 1.4584x over previous
#include <cuda_runtime.h>
#include <math.h>

#define Bsz 128
#define Tsz 1024
#define Fsz 128
#define Hsz 256
#define KC  32
#define NTHR 128
#define TLAST 1020

typedef unsigned long long ull;

// Persistent state
__device__ float g_h[3][2][Bsz][Hsz];   // double-buffered hidden state per layer
__device__ float g_c[3][Bsz][Hsz];      // cell state
__device__ unsigned g_cnt[8][32];       // per-group barrier counters (padded)
__device__ volatile unsigned g_gen[8][32];

struct SmemT {
    float w[2][KC][68];   // [buf][k][gate*16 + j], padded 64->68 (conflict-free)
    float in[2][KC][20];  // [buf][k][b], padded 16->20
};

__device__ __forceinline__ ull ffma2(ull a, ull b, ull c) {
    ull d; asm("fma.rn.f32x2 %0, %1, %2, %3;" : "=l"(d) : "l"(a), "l"(b), "l"(c)); return d;
}
__device__ __forceinline__ ull fadd2(ull a, ull b) {
    ull d; asm("add.rn.f32x2 %0, %1, %2;" : "=l"(d) : "l"(a), "l"(b)); return d;
}
__device__ __forceinline__ ull pack2(float x) {
    ull d; asm("mov.b64 %0, {%1, %1};" : "=l"(d) : "f"(x)); return d;
}
__device__ __forceinline__ float2 unpack2(ull v) {
    float2 r; asm("mov.b64 {%0, %1}, %2;" : "=f"(r.x), "=f"(r.y) : "l"(v)); return r;
}
__device__ __forceinline__ float sigf(float x) { return 1.f / (1.f + __expf(-x)); }
__device__ __forceinline__ float tanh_fast(float x) { return fmaf(2.f, sigf(2.f * x), -1.f); }

// 16-block group barrier (blocks sharing one batch slice)
__device__ __forceinline__ void group_sync(int bg, unsigned &gen) {
    __syncthreads();
    if (threadIdx.x == 0) {
        gen++;
        __threadfence();
        unsigned old = atomicAdd(&g_cnt[bg][0], 1u);
        if (old == 15u) {
            g_cnt[bg][0] = 0u;
            __threadfence();
            atomicExch((unsigned*)&g_gen[bg][0], gen);
        } else {
            while (g_gen[bg][0] != gen) { }
        }
        __threadfence();
    }
    __syncthreads();
}

// One GEMM segment: acc[g][u] (f32x2 over j-pair) += inp[b, :K] * W[n, :K]^T.
// Streamed in KC chunks, double-buffered smem. 8-way k-split (ks = tid&7).
__device__ __forceinline__ void do_segment(SmemT* s,
    const float* __restrict__ W, int K,
    const float* __restrict__ inp, long strideB, bool coh,
    int jbase, int bbase, int ks, int bq, int jp,
    ull acc[4][8])
{
    const int tid = threadIdx.x;
    const int wg  = tid >> 5;            // gate (warp id)
    const int wj  = (tid >> 1) & 15;     // j within tile
    const int wq  = (tid & 1) * 4;       // k float4-interleave (conflict-free STS)
    const int sb  = tid >> 3;            // batch row for input staging
    const int sq  = tid & 7;             // k quad for input staging
    const int wcol = wg * 16 + wj;
    const float* wrow = W + (size_t)(wg * Hsz + jbase + wj) * K;
    const float* irow = inp + (size_t)(bbase + sb) * strideB + sq * 4;
    const int nchunk = K / KC;

    float4 wv[4]; float4 iv;
    // prologue: chunk 0 -> buffer 0
#pragma unroll
    for (int q = 0; q < 4; q++) wv[q] = __ldg((const float4*)(wrow + q * 8 + wq));
    iv = coh ? __ldcg((const float4*)irow) : __ldg((const float4*)irow);
#pragma unroll
    for (int q = 0; q < 4; q++) {
        const int kb = q * 8 + wq;
        s->w[0][kb + 0][wcol] = wv[q].x;
        s->w[0][kb + 1][wcol] = wv[q].y;
        s->w[0][kb + 2][wcol] = wv[q].z;
        s->w[0][kb + 3][wcol] = wv[q].w;
    }
    s->in[0][sq * 4 + 0][sb] = iv.x;
    s->in[0][sq * 4 + 1][sb] = iv.y;
    s->in[0][sq * 4 + 2][sb] = iv.z;
    s->in[0][sq * 4 + 3][sb] = iv.w;
    __syncthreads();

    for (int ci = 0; ci < nchunk; ci++) {
        const int cur = ci & 1;
        const int nxt = cur ^ 1;
        const bool more = (ci + 1 < nchunk);
        if (more) {
            const int k0 = (ci + 1) * KC;
#pragma unroll
            for (int q = 0; q < 4; q++) wv[q] = __ldg((const float4*)(wrow + k0 + q * 8 + wq));
            iv = coh ? __ldcg((const float4*)(irow + k0)) : __ldg((const float4*)(irow + k0));
        }
#pragma unroll
        for (int kq = 0; kq < 4; kq++) {
            const int k = kq * 8 + ks;
            const float4 x0 = *(const float4*)&s->in[cur][k][bq * 8];
            const float4 x1 = *(const float4*)&s->in[cur][k][bq * 8 + 4];
            const ull w0 = *(const ull*)&s->w[cur][k][jp * 2];
            const ull w1 = *(const ull*)&s->w[cur][k][16 + jp * 2];
            const ull w2 = *(const ull*)&s->w[cur][k][32 + jp * 2];
            const ull w3 = *(const ull*)&s->w[cur][k][48 + jp * 2];
            ull xx;
            xx = pack2(x0.x);
            acc[0][0]=ffma2(w0,xx,acc[0][0]); acc[1][0]=ffma2(w1,xx,acc[1][0]);
            acc[2][0]=ffma2(w2,xx,acc[2][0]); acc[3][0]=ffma2(w3,xx,acc[3][0]);
            xx = pack2(x0.y);
            acc[0][1]=ffma2(w0,xx,acc[0][1]); acc[1][1]=ffma2(w1,xx,acc[1][1]);
            acc[2][1]=ffma2(w2,xx,acc[2][1]); acc[3][1]=ffma2(w3,xx,acc[3][1]);
            xx = pack2(x0.z);
            acc[0][2]=ffma2(w0,xx,acc[0][2]); acc[1][2]=ffma2(w1,xx,acc[1][2]);
            acc[2][2]=ffma2(w2,xx,acc[2][2]); acc[3][2]=ffma2(w3,xx,acc[3][2]);
            xx = pack2(x0.w);
            acc[0][3]=ffma2(w0,xx,acc[0][3]); acc[1][3]=ffma2(w1,xx,acc[1][3]);
            acc[2][3]=ffma2(w2,xx,acc[2][3]); acc[3][3]=ffma2(w3,xx,acc[3][3]);
            xx = pack2(x1.x);
            acc[0][4]=ffma2(w0,xx,acc[0][4]); acc[1][4]=ffma2(w1,xx,acc[1][4]);
            acc[2][4]=ffma2(w2,xx,acc[2][4]); acc[3][4]=ffma2(w3,xx,acc[3][4]);
            xx = pack2(x1.y);
            acc[0][5]=ffma2(w0,xx,acc[0][5]); acc[1][5]=ffma2(w1,xx,acc[1][5]);
            acc[2][5]=ffma2(w2,xx,acc[2][5]); acc[3][5]=ffma2(w3,xx,acc[3][5]);
            xx = pack2(x1.z);
            acc[0][6]=ffma2(w0,xx,acc[0][6]); acc[1][6]=ffma2(w1,xx,acc[1][6]);
            acc[2][6]=ffma2(w2,xx,acc[2][6]); acc[3][6]=ffma2(w3,xx,acc[3][6]);
            xx = pack2(x1.w);
            acc[0][7]=ffma2(w0,xx,acc[0][7]); acc[1][7]=ffma2(w1,xx,acc[1][7]);
            acc[2][7]=ffma2(w2,xx,acc[2][7]); acc[3][7]=ffma2(w3,xx,acc[3][7]);
        }
        if (more) {
            // buf[nxt] last read before previous iteration's __syncthreads
#pragma unroll
            for (int q = 0; q < 4; q++) {
                const int kb = q * 8 + wq;
                s->w[nxt][kb + 0][wcol] = wv[q].x;
                s->w[nxt][kb + 1][wcol] = wv[q].y;
                s->w[nxt][kb + 2][wcol] = wv[q].z;
                s->w[nxt][kb + 3][wcol] = wv[q].w;
            }
            s->in[nxt][sq * 4 + 0][sb] = iv.x;
            s->in[nxt][sq * 4 + 1][sb] = iv.y;
            s->in[nxt][sq * 4 + 2][sb] = iv.z;
            s->in[nxt][sq * 4 + 3][sb] = iv.w;
        }
        __syncthreads();
    }
}

__device__ __forceinline__ void layer_update(SmemT* s,
    const float* __restrict__ WA, int KA, const float* __restrict__ inpA, long strideA, bool cohA,
    const float* __restrict__ WB, const float* __restrict__ inpB,
    const float bsum[4][2],
    float* __restrict__ cbase, float* __restrict__ hout,
    float* __restrict__ yout, int t0,
    int jbase, int bbase)
{
    const int tid = threadIdx.x;
    const int ks = tid & 7;
    const int bq = (tid >> 3) & 1;
    const int jp = tid >> 4;

    ull acc[4][8];
#pragma unroll
    for (int g = 0; g < 4; g++)
#pragma unroll
        for (int u = 0; u < 8; u++) acc[g][u] = 0ull;

    do_segment(s, WA, KA,  inpA, strideA, cohA, jbase, bbase, ks, bq, jp, acc);
    do_segment(s, WB, Hsz, inpB, Hsz,     true,  jbase, bbase, ks, bq, jp, acc);

    // reduce 8-way k-split across lanes (bits 0..2)
#pragma unroll
    for (int g = 0; g < 4; g++)
#pragma unroll
        for (int u = 0; u < 8; u++) {
            ull v = acc[g][u];
            v = fadd2(v, __shfl_xor_sync(0xffffffffu, v, 1));
            v = fadd2(v, __shfl_xor_sync(0xffffffffu, v, 2));
            v = fadd2(v, __shfl_xor_sync(0xffffffffu, v, 4));
            acc[g][u] = v;
        }

    // lane ks owns batch u == ks (static SEL chain, no dynamic reg index)
    ull gsel[4];
#pragma unroll
    for (int g = 0; g < 4; g++) {
        ull v = acc[g][0];
#pragma unroll
        for (int u = 1; u < 8; u++) if (ks == u) v = acc[g][u];
        gsel[g] = v;
    }

    const int b = bbase + bq * 8 + ks;
    const float2 gi = unpack2(gsel[0]);
    const float2 gf = unpack2(gsel[1]);
    const float2 gg = unpack2(gsel[2]);
    const float2 go = unpack2(gsel[3]);
#pragma unroll
    for (int p = 0; p < 2; p++) {
        const int j = jbase + jp * 2 + p;
        const float vi = (p ? gi.y : gi.x) + bsum[0][p];
        const float vf = (p ? gf.y : gf.x) + bsum[1][p];
        const float vg = (p ? gg.y : gg.x) + bsum[2][p];
        const float vo = (p ? go.y : go.x) + bsum[3][p];
        const float i_ = sigf(vi);
        const float f_ = sigf(vf);
        const float g_ = tanh_fast(vg);
        const float o_ = sigf(vo);
        const float cn = fmaf(f_, cbase[b * Hsz + j], i_ * g_);
        const float hn = o_ * tanh_fast(cn);
        cbase[b * Hsz + j] = cn;
        hout[b * Hsz + j]  = hn;
        if (yout) {
#pragma unroll
            for (int u = 0; u < 4; u++)
                yout[((size_t)b * Tsz + (t0 + u)) * Hsz + j] = hn;
        }
    }
}

__global__ void __launch_bounds__(NTHR, 1) drnn_persistent(
    const float* __restrict__ x,
    const float* __restrict__ Wih0, const float* __restrict__ Whh0,
    const float* __restrict__ bih0, const float* __restrict__ bhh0,
    const float* __restrict__ Wih1, const float* __restrict__ Whh1,
    const float* __restrict__ bih1, const float* __restrict__ bhh1,
    const float* __restrict__ Wih2, const float* __restrict__ Whh2,
    const float* __restrict__ bih2, const float* __restrict__ bhh2,
    float* __restrict__ y)
{
    __shared__ SmemT s;
    const int bid = blockIdx.x;
    const int jg = bid & 15;
    const int bg = bid >> 4;
    const int jbase = jg * 16;
    const int bbase = bg * 16;
    const int tid = threadIdx.x;
    const int jp = tid >> 4;

    unsigned gen = 0;
    if (jg == 0 && tid == 0) g_gen[bg][0] = 0;  // reset strictly precedes this block's arrive

    // zero this group's state slices
    for (int i = tid; i < 256; i += NTHR) {
        const int jj = jbase + (i & 15);
        const int bb = bbase + (i >> 4);
#pragma unroll
        for (int l = 0; l < 3; l++) {
            g_h[l][0][bb][jj] = 0.f;
            g_h[l][1][bb][jj] = 0.f;
            g_c[l][bb][jj]    = 0.f;
        }
    }

    // hoist per-thread bias sums out of the time loop
    float bs[3][4][2];
#pragma unroll
    for (int g = 0; g < 4; g++)
#pragma unroll
        for (int p = 0; p < 2; p++) {
            const int j = jbase + jp * 2 + p;
            bs[0][g][p] = __ldg(&bih0[g * Hsz + j]) + __ldg(&bhh0[g * Hsz + j]);
            bs[1][g][p] = __ldg(&bih1[g * Hsz + j]) + __ldg(&bhh1[g * Hsz + j]);
            bs[2][g][p] = __ldg(&bih2[g * Hsz + j]) + __ldg(&bhh2[g * Hsz + j]);
        }

    group_sync(bg, gen);

    int p0 = 0, p1 = 0, p2 = 0;
    for (int t = 0; t <= TLAST; t++) {
        // layer 0 — every step
        layer_update(&s, Wih0, Fsz, x + (size_t)t * Fsz, (long)Tsz * Fsz, false,
                     Whh0, &g_h[0][p0][0][0], bs[0],
                     &g_c[0][0][0], &g_h[0][p0 ^ 1][0][0], nullptr, 0,
                     jbase, bbase);
        p0 ^= 1;
        group_sync(bg, gen);

        if ((t & 1) == 0) {
            // layer 1 — every 2nd step (reads h0 just written)
            layer_update(&s, Wih1, Hsz, &g_h[0][p0][0][0], Hsz, true,
                         Whh1, &g_h[1][p1][0][0], bs[1],
                         &g_c[1][0][0], &g_h[1][p1 ^ 1][0][0], nullptr, 0,
                         jbase, bbase);
            p1 ^= 1;
            if ((t & 3) == 0) {
                group_sync(bg, gen);   // layer2 consumes h1 immediately
                layer_update(&s, Wih2, Hsz, &g_h[1][p1][0][0], Hsz, true,
                             Whh2, &g_h[2][p2][0][0], bs[2],
                             &g_c[2][0][0], &g_h[2][p2 ^ 1][0][0], y, t,
                             jbase, bbase);
                p2 ^= 1;
            }
            // no barrier needed here: next consumers are separated by the
            // barrier after the following layer-0 update
        }
    }
}

extern "C" void kernel_launch(void* const* d_in, const int* in_sizes, int n_in,
                              void* d_out, int out_size) {
    const float* x    = (const float*)d_in[0];
    const float* Wih0 = (const float*)d_in[1];
    const float* Whh0 = (const float*)d_in[2];
    const float* bih0 = (const float*)d_in[3];
    const float* bhh0 = (const float*)d_in[4];
    const float* Wih1 = (const float*)d_in[5];
    const float* Whh1 = (const float*)d_in[6];
    const float* bih1 = (const float*)d_in[7];
    const float* bhh1 = (const float*)d_in[8];
    const float* Wih2 = (const float*)d_in[9];
    const float* Whh2 = (const float*)d_in[10];
    const float* bih2 = (const float*)d_in[11];
    const float* bhh2 = (const float*)d_in[12];
    float* y = (float*)d_out;

    drnn_persistent<<<128, NTHR>>>(x,
        Wih0, Whh0, bih0, bhh0,
        Wih1, Whh1, bih1, bhh1,
        Wih2, Whh2, bih2, bhh2, y);
}

// round 8
// speedup vs baseline: 1.8883x; 1.2948x over previous
#include <cuda_runtime.h>

#define Bsz 128
#define Tsz 1024
#define Fsz 128
#define Hsz 256
#define KC  64
#define NTHR 256
#define TLAST 1020

typedef unsigned long long ull;

// Persistent state: h double-buffered per layer. (c lives in registers.)
__device__ float g_h[3][2][Bsz][Hsz];
__device__ unsigned g_cnt[8][32];
__device__ volatile unsigned g_gen[8][32];

#define WSTRIDE 66            // 64 cols (4g x 16j) + 2 pad
#define ISTRIDE 17            // 16 float2 + 1 pad

struct SmemT {
    float  w[2][KC][WSTRIDE];     // [buf][k][g*16 + j]
    float2 in2[2][KC][ISTRIDE];   // [buf][k][b], value duplicated (x,x)
};
#define SMEM_BYTES ((int)sizeof(SmemT))

__device__ __forceinline__ ull ffma2(ull a, ull b, ull c) {
    ull d; asm("fma.rn.f32x2 %0, %1, %2, %3;" : "=l"(d) : "l"(a), "l"(b), "l"(c)); return d;
}
__device__ __forceinline__ ull fadd2(ull a, ull b) {
    ull d; asm("add.rn.f32x2 %0, %1, %2;" : "=l"(d) : "l"(a), "l"(b)); return d;
}
__device__ __forceinline__ float2 unpack2(ull v) {
    float2 r; asm("mov.b64 {%0, %1}, %2;" : "=f"(r.x), "=f"(r.y) : "l"(v)); return r;
}
__device__ __forceinline__ float sigf(float x) { return 1.f / (1.f + __expf(-x)); }
__device__ __forceinline__ float tanh_fast(float x) { return fmaf(2.f, sigf(2.f * x), -1.f); }

// 16-block group barrier (blocks sharing one batch slice)
__device__ __forceinline__ void group_sync(int bg, unsigned &gen) {
    __syncthreads();
    if (threadIdx.x == 0) {
        gen++;
        __threadfence();
        unsigned old = atomicAdd(&g_cnt[bg][0], 1u);
        if (old == 15u) {
            g_cnt[bg][0] = 0u;
            __threadfence();
            atomicExch((unsigned*)&g_gen[bg][0], gen);
        } else {
            while (g_gen[bg][0] != gen) { }
        }
        __threadfence();
    }
    __syncthreads();
}

// One GEMM segment: acc[g][u] (f32x2 over j-pair) += inp[b,:K] * W[n,:K]^T.
// KC-chunked, double-buffered. 16-way k-split (ks = tid & 15).
__device__ __forceinline__ void do_segment(SmemT* s,
    const float* __restrict__ W, int K,
    const float* __restrict__ inp, long strideB, bool coh,
    int jbase, int bbase, int ks, int bh, int jp,
    ull acc[4][8])
{
    const int tid = threadIdx.x;
    // weight staging role: 64 rows (4g x 16j) x 64 k, 4 float4/thread (k-interleaved)
    const int wg = tid >> 6;
    const int wj = (tid >> 2) & 15;
    const int wk = tid & 3;
    const int wcol = wg * 16 + wj;
    // input staging role: 16 b x 64 k, 1 float4/thread, stored duplicated
    const int sb = tid & 15;
    const int sq = tid >> 4;      // k-quad 0..15
    const float* wrow = W + (size_t)(wg * Hsz + jbase + wj) * K + wk * 4;
    const float* irow = inp + (size_t)(bbase + sb) * strideB + sq * 4;
    const int nchunk = K / KC;

    float4 wv[4]; float4 iv;
    // prologue: chunk 0 -> buffer 0
#pragma unroll
    for (int q = 0; q < 4; q++) wv[q] = __ldg((const float4*)(wrow + q * 16));
    iv = coh ? __ldcg((const float4*)irow) : __ldg((const float4*)irow);
#pragma unroll
    for (int q = 0; q < 4; q++) {
        const int kb = wk * 4 + q * 16;
        s->w[0][kb + 0][wcol] = wv[q].x;
        s->w[0][kb + 1][wcol] = wv[q].y;
        s->w[0][kb + 2][wcol] = wv[q].z;
        s->w[0][kb + 3][wcol] = wv[q].w;
    }
    s->in2[0][sq * 4 + 0][sb] = make_float2(iv.x, iv.x);
    s->in2[0][sq * 4 + 1][sb] = make_float2(iv.y, iv.y);
    s->in2[0][sq * 4 + 2][sb] = make_float2(iv.z, iv.z);
    s->in2[0][sq * 4 + 3][sb] = make_float2(iv.w, iv.w);
    __syncthreads();

    for (int ci = 0; ci < nchunk; ci++) {
        const int cur = ci & 1;
        const int nxt = cur ^ 1;
        const bool more = (ci + 1 < nchunk);
        if (more) {
            const int k0 = (ci + 1) * KC;
#pragma unroll
            for (int q = 0; q < 4; q++) wv[q] = __ldg((const float4*)(wrow + k0 + q * 16));
            iv = coh ? __ldcg((const float4*)(irow + k0)) : __ldg((const float4*)(irow + k0));
        }
#pragma unroll
        for (int kq = 0; kq < 4; kq++) {
            const int k = kq * 16 + ks;
            const ull w0 = *(const ull*)&s->w[cur][k][jp * 2];
            const ull w1 = *(const ull*)&s->w[cur][k][16 + jp * 2];
            const ull w2 = *(const ull*)&s->w[cur][k][32 + jp * 2];
            const ull w3 = *(const ull*)&s->w[cur][k][48 + jp * 2];
#pragma unroll
            for (int u = 0; u < 8; u++) {
                const ull xx = *(const ull*)&s->in2[cur][k][bh * 8 + u];
                acc[0][u] = ffma2(w0, xx, acc[0][u]);
                acc[1][u] = ffma2(w1, xx, acc[1][u]);
                acc[2][u] = ffma2(w2, xx, acc[2][u]);
                acc[3][u] = ffma2(w3, xx, acc[3][u]);
            }
        }
        if (more) {
            // buf[nxt] last read before the previous iteration's __syncthreads
#pragma unroll
            for (int q = 0; q < 4; q++) {
                const int kb = wk * 4 + q * 16;
                s->w[nxt][kb + 0][wcol] = wv[q].x;
                s->w[nxt][kb + 1][wcol] = wv[q].y;
                s->w[nxt][kb + 2][wcol] = wv[q].z;
                s->w[nxt][kb + 3][wcol] = wv[q].w;
            }
            s->in2[nxt][sq * 4 + 0][sb] = make_float2(iv.x, iv.x);
            s->in2[nxt][sq * 4 + 1][sb] = make_float2(iv.y, iv.y);
            s->in2[nxt][sq * 4 + 2][sb] = make_float2(iv.z, iv.z);
            s->in2[nxt][sq * 4 + 3][sb] = make_float2(iv.w, iv.w);
        }
        __syncthreads();
    }
}

__device__ __forceinline__ void layer_update(SmemT* s,
    const float* __restrict__ WA, int KA, const float* __restrict__ inpA, long strideA, bool cohA,
    const float* __restrict__ WB, const float* __restrict__ inpB,
    const float bsum[4], float& creg,
    float* __restrict__ hout, float* __restrict__ yout, int t0,
    int jbase, int bbase, int ks, int bh, int jp, int b, int j)
{
    ull acc[4][8];
#pragma unroll
    for (int g = 0; g < 4; g++)
#pragma unroll
        for (int u = 0; u < 8; u++) acc[g][u] = 0ull;

    do_segment(s, WA, KA,  inpA, strideA, cohA, jbase, bbase, ks, bh, jp, acc);
    do_segment(s, WB, Hsz, inpB, Hsz,     true,  jbase, bbase, ks, bh, jp, acc);

    // u-compressing butterfly over k-split lanes; lane ks ends owning u = ks&7
    const bool h1 = (ks & 1) != 0;
    const bool h2 = (ks & 2) != 0;
    const bool h4 = (ks & 4) != 0;
    ull a1[4][4], a2[4][2], a3[4];
#pragma unroll
    for (int g = 0; g < 4; g++)
#pragma unroll
        for (int q = 0; q < 4; q++) {
            const ull mine  = h1 ? acc[g][2*q+1] : acc[g][2*q];
            const ull other = h1 ? acc[g][2*q]   : acc[g][2*q+1];
            a1[g][q] = fadd2(mine, __shfl_xor_sync(0xffffffffu, other, 1));
        }
#pragma unroll
    for (int g = 0; g < 4; g++)
#pragma unroll
        for (int q = 0; q < 2; q++) {
            const ull mine  = h2 ? a1[g][2*q+1] : a1[g][2*q];
            const ull other = h2 ? a1[g][2*q]   : a1[g][2*q+1];
            a2[g][q] = fadd2(mine, __shfl_xor_sync(0xffffffffu, other, 2));
        }
#pragma unroll
    for (int g = 0; g < 4; g++) {
        const ull mine  = h4 ? a2[g][1] : a2[g][0];
        const ull other = h4 ? a2[g][0] : a2[g][1];
        a3[g] = fadd2(mine, __shfl_xor_sync(0xffffffffu, other, 4));
        a3[g] = fadd2(a3[g], __shfl_xor_sync(0xffffffffu, a3[g], 8));
    }

    // extract this thread's j (p = ks>>3 selects f32x2 half)
    const int p = ks >> 3;
    const float2 ri = unpack2(a3[0]);
    const float2 rf = unpack2(a3[1]);
    const float2 rg = unpack2(a3[2]);
    const float2 ro = unpack2(a3[3]);
    const float vi = (p ? ri.y : ri.x) + bsum[0];
    const float vf = (p ? rf.y : rf.x) + bsum[1];
    const float vg = (p ? rg.y : rg.x) + bsum[2];
    const float vo = (p ? ro.y : ro.x) + bsum[3];
    const float i_ = sigf(vi);
    const float f_ = sigf(vf);
    const float g_ = tanh_fast(vg);
    const float o_ = sigf(vo);
    const float cn = fmaf(f_, creg, i_ * g_);
    const float hn = o_ * tanh_fast(cn);
    creg = cn;
    hout[b * Hsz + j] = hn;
    if (yout) {
#pragma unroll
        for (int u = 0; u < 4; u++)
            yout[((size_t)b * Tsz + (t0 + u)) * Hsz + j] = hn;
    }
}

__global__ void __launch_bounds__(NTHR, 1) drnn_persistent(
    const float* __restrict__ x,
    const float* __restrict__ Wih0, const float* __restrict__ Whh0,
    const float* __restrict__ bih0, const float* __restrict__ bhh0,
    const float* __restrict__ Wih1, const float* __restrict__ Whh1,
    const float* __restrict__ bih1, const float* __restrict__ bhh1,
    const float* __restrict__ Wih2, const float* __restrict__ Whh2,
    const float* __restrict__ bih2, const float* __restrict__ bhh2,
    float* __restrict__ y)
{
    extern __shared__ char smem_raw[];
    SmemT* s = (SmemT*)smem_raw;
    const int bid = blockIdx.x;
    const int jg = bid & 15;
    const int bg = bid >> 4;
    const int jbase = jg * 16;
    const int bbase = bg * 16;
    const int tid = threadIdx.x;
    const int ks = tid & 15;
    const int jp = (tid >> 4) & 7;
    const int bh = tid >> 7;
    const int b  = bbase + bh * 8 + (ks & 7);
    const int j  = jbase + jp * 2 + (ks >> 3);

    unsigned gen = 0;
    if (jg == 0 && tid == 0) g_gen[bg][0] = 0;

    // zero this block's h slices (one element per thread covers the 16x16 tile)
    {
        const int jj = jbase + (tid & 15);
        const int bb = bbase + (tid >> 4);
#pragma unroll
        for (int l = 0; l < 3; l++) {
            g_h[l][0][bb][jj] = 0.f;
            g_h[l][1][bb][jj] = 0.f;
        }
    }

    // per-thread bias sums (thread owns one j)
    float bs[3][4];
#pragma unroll
    for (int g = 0; g < 4; g++) {
        bs[0][g] = __ldg(&bih0[g * Hsz + j]) + __ldg(&bhh0[g * Hsz + j]);
        bs[1][g] = __ldg(&bih1[g * Hsz + j]) + __ldg(&bhh1[g * Hsz + j]);
        bs[2][g] = __ldg(&bih2[g * Hsz + j]) + __ldg(&bhh2[g * Hsz + j]);
    }
    float c0 = 0.f, c1 = 0.f, c2 = 0.f;

    group_sync(bg, gen);

    int p0 = 0, p1 = 0, p2 = 0;
    for (int t = 0; t <= TLAST; t++) {
        // layer 0 — every step
        layer_update(s, Wih0, Fsz, x + (size_t)t * Fsz, (long)Tsz * Fsz, false,
                     Whh0, &g_h[0][p0][0][0], bs[0], c0,
                     &g_h[0][p0 ^ 1][0][0], nullptr, 0,
                     jbase, bbase, ks, bh, jp, b, j);
        p0 ^= 1;
        group_sync(bg, gen);

        if ((t & 1) == 0) {
            // layer 1 — every 2nd step (reads h0 just published)
            layer_update(s, Wih1, Hsz, &g_h[0][p0][0][0], Hsz, true,
                         Whh1, &g_h[1][p1][0][0], bs[1], c1,
                         &g_h[1][p1 ^ 1][0][0], nullptr, 0,
                         jbase, bbase, ks, bh, jp, b, j);
            p1 ^= 1;
            if ((t & 3) == 0) {
                group_sync(bg, gen);   // publish h1 for layer 2
                layer_update(s, Wih2, Hsz, &g_h[1][p1][0][0], Hsz, true,
                             Whh2, &g_h[2][p2][0][0], bs[2], c2,
                             &g_h[2][p2 ^ 1][0][0], y, t,
                             jbase, bbase, ks, bh, jp, b, j);
                p2 ^= 1;
            }
            // next consumers are separated by the barrier after the next layer-0
        }
    }
}

extern "C" void kernel_launch(void* const* d_in, const int* in_sizes, int n_in,
                              void* d_out, int out_size) {
    const float* x    = (const float*)d_in[0];
    const float* Wih0 = (const float*)d_in[1];
    const float* Whh0 = (const float*)d_in[2];
    const float* bih0 = (const float*)d_in[3];
    const float* bhh0 = (const float*)d_in[4];
    const float* Wih1 = (const float*)d_in[5];
    const float* Whh1 = (const float*)d_in[6];
    const float* bih1 = (const float*)d_in[7];
    const float* bhh1 = (const float*)d_in[8];
    const float* Wih2 = (const float*)d_in[9];
    const float* Whh2 = (const float*)d_in[10];
    const float* bih2 = (const float*)d_in[11];
    const float* bhh2 = (const float*)d_in[12];
    float* y = (float*)d_out;

    cudaFuncSetAttribute(drnn_persistent,
                         cudaFuncAttributeMaxDynamicSharedMemorySize, SMEM_BYTES);

    drnn_persistent<<<128, NTHR, SMEM_BYTES>>>(x,
        Wih0, Whh0, bih0, bhh0,
        Wih1, Whh1, bih1, bhh1,
        Wih2, Whh2, bih2, bhh2, y);
}

// round 9
// speedup vs baseline: 1.9518x; 1.0337x over previous
#include <cuda_runtime.h>

#define Bsz 128
#define Tsz 1024
#define Fsz 128
#define Hsz 256
#define TLAST 1020
#define NTHR 512
#define BJ 8
#define BB 32
#define KC 64
#define ISTRIDE 36   // floats per in_ row (32 + 4 pad), keeps STS.128 at min wavefronts

typedef unsigned long long ull;

// Persistent state
__device__ float g_h[3][2][Bsz][Hsz];
__device__ unsigned g_cnt[4][32];
__device__ volatile unsigned g_gen[4][32];

// Dynamic smem layout (bytes):
//   [0, 180224)          wsm: 1408 k-rows x 16 float2  ([row][jp][g])
//   [180224, 213 - )     union: in_ [2][KC][ISTRIDE] float (18432B)  OR  slab [8][512] float2 (32768B)
//   [212992, 217088)     gsm: [4][32][8] float (4096B)
#define WSM_ROWS 1408
#define UNION_OFF (WSM_ROWS * 16 * 8)            // 180224
#define UNION_BYTES 32768
#define GSM_OFF (UNION_OFF + UNION_BYTES)        // 212992
#define SMEM_TOTAL (GSM_OFF + 4 * 32 * 8 * 4)    // 217088

__device__ __forceinline__ ull ffma2(ull a, ull b, ull c) {
    ull d; asm("fma.rn.f32x2 %0, %1, %2, %3;" : "=l"(d) : "l"(a), "l"(b), "l"(c)); return d;
}
__device__ __forceinline__ ull fadd2(ull a, ull b) {
    ull d; asm("add.rn.f32x2 %0, %1, %2;" : "=l"(d) : "l"(a), "l"(b)); return d;
}
__device__ __forceinline__ ull dup2(float x) {
    ull d; asm("mov.b64 %0, {%1, %1};" : "=l"(d) : "f"(x)); return d;
}
__device__ __forceinline__ float sigf(float x) { return 1.f / (1.f + __expf(-x)); }
__device__ __forceinline__ float tanh_fast(float x) { return fmaf(2.f, sigf(2.f * x), -1.f); }

// 32-block group barrier (blocks sharing one batch slice)
__device__ __forceinline__ void group_sync(int bg, unsigned &gen) {
    __syncthreads();
    if (threadIdx.x == 0) {
        gen++;
        __threadfence();
        unsigned old = atomicAdd(&g_cnt[bg][0], 1u);
        if (old == 31u) {
            g_cnt[bg][0] = 0u;
            __threadfence();
            atomicExch((unsigned*)&g_gen[bg][0], gen);
        } else {
            while (g_gen[bg][0] != gen) { }
        }
        __threadfence();
    }
    __syncthreads();
}

// One fused layer update. Weights are already resident in wsm rows [wbase, wbase+KA+256).
// Inputs streamed through in_ in KC chunks (double buffered).
__device__ __forceinline__ void layer_update(
    const float2* __restrict__ wsm, float* __restrict__ ins,
    float2* __restrict__ slab, float* __restrict__ gsm,
    int wbase, int KA,
    const float* __restrict__ inpA, long strideA, bool cohA,
    const float* __restrict__ inpB,          // stride Hsz, L2-coherent
    const float* __restrict__ bsum,          // [4], valid for tid<256
    float& creg,
    float* __restrict__ hout, float* __restrict__ yout, int t0,
    int jbase, int bbase)
{
    const int tid = threadIdx.x;
    const int lane = tid & 31;
    const int warp = tid >> 5;
    const int kh = warp & 7;      // k-split slot
    const int bH = warp >> 3;     // batch half
    const int jp = lane & 3;      // j-pair
    const int bo = lane >> 2;     // batch pair index within half
    // staging roles
    const int sk = tid & 63;      // k within chunk
    const int sbq = tid >> 6;     // batch quad

    const int nc = (KA + Hsz) / KC;   // 6 (L0) or 8 (L1/2)

    ull acc[8];                   // [g*2 + u]
#pragma unroll
    for (int i = 0; i < 8; i++) acc[i] = 0ull;

    // ---- stage chunk 0 ----
    {
        const float* src = inpA; long bst = strideA; int kc = 0; bool coh = cohA;
        const float* sp = src + (size_t)(bbase + sbq * 4) * bst + kc + sk;
        float4 v;
        v.x = coh ? __ldcg(sp)            : __ldg(sp);
        v.y = coh ? __ldcg(sp + bst)      : __ldg(sp + bst);
        v.z = coh ? __ldcg(sp + 2 * bst)  : __ldg(sp + 2 * bst);
        v.w = coh ? __ldcg(sp + 3 * bst)  : __ldg(sp + 3 * bst);
        *(float4*)(ins + sk * ISTRIDE + sbq * 4) = v;
    }
    __syncthreads();

    for (int c = 0; c < nc; c++) {
        const bool more = (c + 1 < nc);
        float4 nv;
        if (more) {
            const int kt = (c + 1) * KC;
            const float* src; long bst; int kc; bool coh;
            if (kt < KA) { src = inpA; bst = strideA; kc = kt; coh = cohA; }
            else         { src = inpB; bst = Hsz; kc = kt - KA; coh = true; }
            const float* sp = src + (size_t)(bbase + sbq * 4) * bst + kc + sk;
            nv.x = coh ? __ldcg(sp)           : __ldg(sp);
            nv.y = coh ? __ldcg(sp + bst)     : __ldg(sp + bst);
            nv.z = coh ? __ldcg(sp + 2 * bst) : __ldg(sp + 2 * bst);
            nv.w = coh ? __ldcg(sp + 3 * bst) : __ldg(sp + 3 * bst);
        }

        const float2* wrow = wsm + (size_t)(wbase + c * KC) * 16 + jp * 4;
        const float*  xin  = ins + (c & 1) * (KC * ISTRIDE) + bH * 16 + bo * 2;
#pragma unroll
        for (int r = 0; r < 8; r++) {
            const int kl = r * 8 + kh;
            const ulonglong2 wa = *(const ulonglong2*)(wrow + (size_t)kl * 16);      // g0,g1
            const ulonglong2 wb = *(const ulonglong2*)(wrow + (size_t)kl * 16 + 2);  // g2,g3
            const float2 xv = *(const float2*)(xin + kl * ISTRIDE);
            const ull x0 = dup2(xv.x);
            const ull x1 = dup2(xv.y);
            acc[0] = ffma2(wa.x, x0, acc[0]);
            acc[2] = ffma2(wa.y, x0, acc[2]);
            acc[4] = ffma2(wb.x, x0, acc[4]);
            acc[6] = ffma2(wb.y, x0, acc[6]);
            acc[1] = ffma2(wa.x, x1, acc[1]);
            acc[3] = ffma2(wa.y, x1, acc[3]);
            acc[5] = ffma2(wb.x, x1, acc[5]);
            acc[7] = ffma2(wb.y, x1, acc[7]);
        }

        if (more)
            *(float4*)(ins + ((c + 1) & 1) * (KC * ISTRIDE) + sk * ISTRIDE + sbq * 4) = nv;
        __syncthreads();
    }

    // ---- write partials to slab (aliases ins; all compute reads done) ----
    // slab layout float2: [kh][g][bH][u][bo][jp], idx = kh*512 + g*128 + bH*64 + u*32 + bo*4 + jp
    {
        float2* wp = slab + (size_t)kh * 512 + bH * 64 + bo * 4 + jp;
#pragma unroll
        for (int g = 0; g < 4; g++)
#pragma unroll
            for (int u = 0; u < 2; u++)
                *(ull*)(wp + g * 128 + u * 32) = acc[g * 2 + u];
    }
    __syncthreads();

    // ---- phase 1: reduce over kh, write gsm ----
    {
        const int g1 = tid >> 7;
        const int b1 = (tid >> 2) & 31;
        const int jp1 = tid & 3;
        const int bH1 = b1 >> 4, u1 = b1 & 1, bo1 = (b1 >> 1) & 7;
        const float2* sp = slab + g1 * 128 + bH1 * 64 + u1 * 32 + bo1 * 4 + jp1;
        ull sacc = *(const ull*)sp;
#pragma unroll
        for (int k = 1; k < 8; k++) sacc = fadd2(sacc, *(const ull*)(sp + (size_t)k * 512));
        *(ull*)&gsm[((g1 * 32 + b1) * 8) + jp1 * 2] = sacc;
    }
    __syncthreads();

    // ---- phase 2: LSTM cell (tid < 256), one (b, j) each ----
    if (tid < 256) {
        const int b2 = tid >> 3;
        const int j2l = tid & 7;
        const int b = bbase + b2;
        const int j = jbase + j2l;
        const float vi = gsm[(0 * 32 + b2) * 8 + j2l] + bsum[0];
        const float vf = gsm[(1 * 32 + b2) * 8 + j2l] + bsum[1];
        const float vg = gsm[(2 * 32 + b2) * 8 + j2l] + bsum[2];
        const float vo = gsm[(3 * 32 + b2) * 8 + j2l] + bsum[3];
        const float i_ = sigf(vi);
        const float f_ = sigf(vf);
        const float g_ = tanh_fast(vg);
        const float o_ = sigf(vo);
        const float cn = fmaf(f_, creg, i_ * g_);
        const float hn = o_ * tanh_fast(cn);
        creg = cn;
        hout[b * Hsz + j] = hn;
        if (yout) {
#pragma unroll
            for (int u = 0; u < 4; u++)
                yout[((size_t)b * Tsz + (t0 + u)) * Hsz + j] = hn;
        }
    }
}

__global__ void __launch_bounds__(NTHR, 1) drnn_persistent(
    const float* __restrict__ x,
    const float* __restrict__ Wih0, const float* __restrict__ Whh0,
    const float* __restrict__ bih0, const float* __restrict__ bhh0,
    const float* __restrict__ Wih1, const float* __restrict__ Whh1,
    const float* __restrict__ bih1, const float* __restrict__ bhh1,
    const float* __restrict__ Wih2, const float* __restrict__ Whh2,
    const float* __restrict__ bih2, const float* __restrict__ bhh2,
    float* __restrict__ y)
{
    extern __shared__ char sm[];
    float2* wsm  = (float2*)sm;
    float*  ins  = (float*)(sm + UNION_OFF);
    float2* slab = (float2*)(sm + UNION_OFF);
    float*  gsm  = (float*)(sm + GSM_OFF);

    const int tid = threadIdx.x;
    const int bid = blockIdx.x;
    const int jg = bid >> 2;      // 0..31
    const int bg = bid & 3;       // 0..3
    const int jbase = jg * BJ;
    const int bbase = bg * BB;

    unsigned gen = 0;
    if (jg == 0 && tid == 0) g_gen[bg][0] = 0;   // reset strictly precedes this block's arrive

    // ---- load all weights into resident smem (once) ----
    for (int e = tid; e < WSM_ROWS * 16; e += NTHR) {
        const int row = e >> 4;
        const int q = e & 15;
        const int jpq = q >> 2, gq = q & 3;
        const float* W; int K, k;
        if      (row <  128) { W = Wih0; K = Fsz; k = row;        }
        else if (row <  384) { W = Whh0; K = Hsz; k = row - 128;  }
        else if (row <  640) { W = Wih1; K = Hsz; k = row - 384;  }
        else if (row <  896) { W = Whh1; K = Hsz; k = row - 640;  }
        else if (row < 1152) { W = Wih2; K = Hsz; k = row - 896;  }
        else                 { W = Whh2; K = Hsz; k = row - 1152; }
        const int n = gq * Hsz + jbase + jpq * 2;
        float2 v;
        v.x = __ldg(&W[(size_t)n * K + k]);
        v.y = __ldg(&W[(size_t)(n + 1) * K + k]);
        wsm[(size_t)row * 16 + jpq * 4 + gq] = v;
    }

    // ---- zero h state for this block's tile; bias sums; c regs ----
    float bs[3][4];
    float c0 = 0.f, c1 = 0.f, c2 = 0.f;
    if (tid < 256) {
        const int b2 = tid >> 3;
        const int j2l = tid & 7;
        const int b = bbase + b2;
        const int j = jbase + j2l;
#pragma unroll
        for (int l = 0; l < 3; l++) {
            g_h[l][0][b][j] = 0.f;
            g_h[l][1][b][j] = 0.f;
        }
#pragma unroll
        for (int g = 0; g < 4; g++) {
            bs[0][g] = __ldg(&bih0[g * Hsz + j]) + __ldg(&bhh0[g * Hsz + j]);
            bs[1][g] = __ldg(&bih1[g * Hsz + j]) + __ldg(&bhh1[g * Hsz + j]);
            bs[2][g] = __ldg(&bih2[g * Hsz + j]) + __ldg(&bhh2[g * Hsz + j]);
        }
    } else {
#pragma unroll
        for (int l = 0; l < 3; l++)
#pragma unroll
            for (int g = 0; g < 4; g++) bs[l][g] = 0.f;
    }

    group_sync(bg, gen);

    int p0 = 0, p1 = 0, p2 = 0;
    for (int t = 0; t <= TLAST; t++) {
        // layer 0 — every step. wsm rows [0,384): Wih0 (k<128) then Whh0.
        layer_update(wsm, ins, slab, gsm, /*wbase*/0, /*KA*/Fsz,
                     x + (size_t)t * Fsz, (long)Tsz * Fsz, false,
                     &g_h[0][p0][0][0],
                     bs[0], c0,
                     &g_h[0][p0 ^ 1][0][0], nullptr, 0, jbase, bbase);
        p0 ^= 1;
        group_sync(bg, gen);

        if ((t & 1) == 0) {
            // layer 1 — every 2nd step. rows [384,896).
            layer_update(wsm, ins, slab, gsm, 384, Hsz,
                         &g_h[0][p0][0][0], Hsz, true,
                         &g_h[1][p1][0][0],
                         bs[1], c1,
                         &g_h[1][p1 ^ 1][0][0], nullptr, 0, jbase, bbase);
            p1 ^= 1;
            if ((t & 3) == 0) {
                group_sync(bg, gen);   // publish h1 for layer 2
                // layer 2 — every 4th step. rows [896,1408).
                layer_update(wsm, ins, slab, gsm, 896, Hsz,
                             &g_h[1][p1][0][0], Hsz, true,
                             &g_h[2][p2][0][0],
                             bs[2], c2,
                             &g_h[2][p2 ^ 1][0][0], y, t, jbase, bbase);
                p2 ^= 1;
            }
            // later consumers are separated by the barrier after the next layer-0
        }
    }
}

extern "C" void kernel_launch(void* const* d_in, const int* in_sizes, int n_in,
                              void* d_out, int out_size) {
    const float* x    = (const float*)d_in[0];
    const float* Wih0 = (const float*)d_in[1];
    const float* Whh0 = (const float*)d_in[2];
    const float* bih0 = (const float*)d_in[3];
    const float* bhh0 = (const float*)d_in[4];
    const float* Wih1 = (const float*)d_in[5];
    const float* Whh1 = (const float*)d_in[6];
    const float* bih1 = (const float*)d_in[7];
    const float* bhh1 = (const float*)d_in[8];
    const float* Wih2 = (const float*)d_in[9];
    const float* Whh2 = (const float*)d_in[10];
    const float* bih2 = (const float*)d_in[11];
    const float* bhh2 = (const float*)d_in[12];
    float* y = (float*)d_out;

    cudaFuncSetAttribute(drnn_persistent,
                         cudaFuncAttributeMaxDynamicSharedMemorySize, SMEM_TOTAL);

    drnn_persistent<<<128, NTHR, SMEM_TOTAL>>>(x,
        Wih0, Whh0, bih0, bhh0,
        Wih1, Whh1, bih1, bhh1,
        Wih2, Whh2, bih2, bhh2, y);
}

// round 10
// speedup vs baseline: 2.0366x; 1.0435x over previous
#include <cuda_runtime.h>

#define Bsz 128
#define Tsz 1024
#define Fsz 128
#define Hsz 256
#define TLAST 1020
#define NTHR 512
#define PF 8

typedef unsigned long long ull;

// Persistent state, transposed + duplicated: element [k][b] = (v, v)
__device__ float2 g_hTd[3][2][Hsz][Bsz];
__device__ float2 g_xTd[(size_t)Tsz * Fsz * Bsz];   // [t][f][b] duplicated
__device__ unsigned g_cnt[4][32];
__device__ volatile unsigned g_gen[4][32];

// smem: weights resident (1408 rows x 16 float2 = 128B/row), then slab, then gsm
#define WSM_ROWS 1408
#define SLAB_OFF (WSM_ROWS * 16 * 8)            // 180224
#define GSM_OFF  (SLAB_OFF + 32768)             // 212992
#define SMEM_TOTAL (GSM_OFF + 4096)             // 217088

__device__ __forceinline__ ull ffma2(ull a, ull b, ull c) {
    ull d; asm("fma.rn.f32x2 %0, %1, %2, %3;" : "=l"(d) : "l"(a), "l"(b), "l"(c)); return d;
}
__device__ __forceinline__ ull fadd2(ull a, ull b) {
    ull d; asm("add.rn.f32x2 %0, %1, %2;" : "=l"(d) : "l"(a), "l"(b)); return d;
}
__device__ __forceinline__ float sigf(float x) { return 1.f / (1.f + __expf(-x)); }
__device__ __forceinline__ float tanh_fast(float x) { return fmaf(2.f, sigf(2.f * x), -1.f); }

// x transpose+duplicate: x[B][T][F] -> g_xTd[t][f][b] = (v,v)
__global__ void transpose_x(const float* __restrict__ x) {
    __shared__ float tile[32][33];
    const int t  = blockIdx.x;
    const int f0 = blockIdx.y * 32;
    const int b0 = blockIdx.z * 32;
    const int tx = threadIdx.x, ty = threadIdx.y;
#pragma unroll
    for (int i = 0; i < 4; i++) {
        const int b = b0 + ty * 4 + i;
        tile[ty * 4 + i][tx] = x[(size_t)b * Tsz * Fsz + (size_t)t * Fsz + f0 + tx];
    }
    __syncthreads();
#pragma unroll
    for (int i = 0; i < 4; i++) {
        const int f = f0 + ty * 4 + i;
        const float v = tile[tx][ty * 4 + i];
        g_xTd[(size_t)t * Fsz * Bsz + (size_t)f * Bsz + b0 + tx] = make_float2(v, v);
    }
}

// 32-block group barrier (blocks sharing one batch slice)
__device__ __forceinline__ void group_sync(int bg, unsigned &gen) {
    __syncthreads();
    if (threadIdx.x == 0) {
        gen++;
        __threadfence();
        unsigned old = atomicAdd(&g_cnt[bg][0], 1u);
        if (old == 31u) {
            g_cnt[bg][0] = 0u;
            __threadfence();
            atomicExch((unsigned*)&g_gen[bg][0], gen);
        } else {
            while (g_gen[bg][0] != gen) { }
        }
        __threadfence();
    }
    __syncthreads();
}

// One layer update. Weights resident in wsm rows [wbase, wbase + NKA*8 + 256).
// srcA/srcB: duplicated-transposed inputs [K][Bsz] float2. No syncs in the GEMM.
template <int NKA, bool COHA>
__device__ __forceinline__ void layer_update(
    const float2* __restrict__ wsm, float2* __restrict__ slab, float* __restrict__ gsm,
    int wbase,
    const float2* __restrict__ srcA, const float2* __restrict__ srcB,
    const float* bsum, float& creg,
    float2* __restrict__ houtD, float* __restrict__ yout, int t0,
    int jbase, int bbase)
{
    const int tid  = threadIdx.x;
    const int lane = tid & 31, warp = tid >> 5;
    const int kh = warp & 7, bH = warp >> 3;
    const int jp = lane & 3, bo = lane >> 2;
    constexpr int NK = NKA + 32;

    const int bcol = bbase + bH * 16 + bo * 2;
    const float4* pA = (const float4*)(srcA + (size_t)kh * Bsz + bcol);
    const float4* pB = (const float4*)(srcB + (size_t)kh * Bsz + bcol);
    const float2* wrow = wsm + (size_t)(wbase + kh) * 16 + jp * 4;

    ull acc[8];
#pragma unroll
    for (int i = 0; i < 8; i++) acc[i] = 0ull;

    float4 xbuf[PF];
#pragma unroll
    for (int q = 0; q < PF; q++)
        xbuf[q] = COHA ? __ldcg(pA + (size_t)q * 4 * Bsz)
                       : __ldg (pA + (size_t)q * 4 * Bsz);

#pragma unroll
    for (int r = 0; r < NK; r++) {
        const int q = r % PF;
        const ulonglong2 wa = *(const ulonglong2*)(wrow + (size_t)r * 128);
        const ulonglong2 wb = *(const ulonglong2*)(wrow + (size_t)r * 128 + 2);
        const ull x0 = ((const ull*)&xbuf[q])[0];
        const ull x1 = ((const ull*)&xbuf[q])[1];
        acc[0] = ffma2(wa.x, x0, acc[0]); acc[1] = ffma2(wa.x, x1, acc[1]);
        acc[2] = ffma2(wa.y, x0, acc[2]); acc[3] = ffma2(wa.y, x1, acc[3]);
        acc[4] = ffma2(wb.x, x0, acc[4]); acc[5] = ffma2(wb.x, x1, acc[5]);
        acc[6] = ffma2(wb.y, x0, acc[6]); acc[7] = ffma2(wb.y, x1, acc[7]);
        const int pf = r + PF;
        if (pf < NK) {
            if (pf < NKA)
                xbuf[q] = COHA ? __ldcg(pA + (size_t)pf * 4 * Bsz)
                               : __ldg (pA + (size_t)pf * 4 * Bsz);
            else
                xbuf[q] = __ldcg(pB + (size_t)(pf - NKA) * 4 * Bsz);
        }
    }

    // ---- reduce over kh warps via slab ----
    {
        float2* wp = slab + (size_t)kh * 512 + bH * 64 + bo * 4 + jp;
#pragma unroll
        for (int g = 0; g < 4; g++)
#pragma unroll
            for (int u = 0; u < 2; u++)
                *(ull*)(wp + g * 128 + u * 32) = acc[g * 2 + u];
    }
    __syncthreads();
    {
        const int g1  = tid >> 7;
        const int b1  = (tid >> 2) & 31;
        const int jp1 = tid & 3;
        const int bH1 = b1 >> 4, u1 = b1 & 1, bo1 = (b1 >> 1) & 7;
        const float2* sp = slab + g1 * 128 + bH1 * 64 + u1 * 32 + bo1 * 4 + jp1;
        ull sacc = *(const ull*)sp;
#pragma unroll
        for (int k = 1; k < 8; k++) sacc = fadd2(sacc, *(const ull*)(sp + (size_t)k * 512));
        *(ull*)&gsm[((g1 * 32 + b1) * 8) + jp1 * 2] = sacc;
    }
    __syncthreads();

    // ---- LSTM cell: tid<256, one (b, j) each; coalesced hTd store ----
    if (tid < 256) {
        const int b2  = tid & 31;
        const int j2l = tid >> 5;
        const int b = bbase + b2;
        const int j = jbase + j2l;
        const float vi = gsm[(0 * 32 + b2) * 8 + j2l] + bsum[0];
        const float vf = gsm[(1 * 32 + b2) * 8 + j2l] + bsum[1];
        const float vg = gsm[(2 * 32 + b2) * 8 + j2l] + bsum[2];
        const float vo = gsm[(3 * 32 + b2) * 8 + j2l] + bsum[3];
        const float i_ = sigf(vi);
        const float f_ = sigf(vf);
        const float g_ = tanh_fast(vg);
        const float o_ = sigf(vo);
        const float cn = fmaf(f_, creg, i_ * g_);
        const float hn = o_ * tanh_fast(cn);
        creg = cn;
        houtD[(size_t)j * Bsz + b] = make_float2(hn, hn);
        if (yout) {
#pragma unroll
            for (int u = 0; u < 4; u++)
                yout[((size_t)b * Tsz + (t0 + u)) * Hsz + j] = hn;
        }
    }
}

__global__ void __launch_bounds__(NTHR, 1) drnn_persistent(
    const float* __restrict__ Wih0, const float* __restrict__ Whh0,
    const float* __restrict__ bih0, const float* __restrict__ bhh0,
    const float* __restrict__ Wih1, const float* __restrict__ Whh1,
    const float* __restrict__ bih1, const float* __restrict__ bhh1,
    const float* __restrict__ Wih2, const float* __restrict__ Whh2,
    const float* __restrict__ bih2, const float* __restrict__ bhh2,
    float* __restrict__ y)
{
    extern __shared__ char sm[];
    float2* wsm  = (float2*)sm;
    float2* slab = (float2*)(sm + SLAB_OFF);
    float*  gsm  = (float*)(sm + GSM_OFF);

    const int tid = threadIdx.x;
    const int bid = blockIdx.x;
    const int jg = bid >> 2;      // 0..31
    const int bg = bid & 3;       // 0..3
    const int jbase = jg * 8;
    const int bbase = bg * 32;

    unsigned gen = 0;
    if (jg == 0 && tid == 0) g_gen[bg][0] = 0;  // fenced inside first group_sync

    // ---- load all weights into resident smem (once) ----
    for (int e = tid; e < WSM_ROWS * 16; e += NTHR) {
        const int row = e >> 4;
        const int q = e & 15;
        const int jpq = q >> 2, gq = q & 3;
        const float* W; int K, k;
        if      (row <  128) { W = Wih0; K = Fsz; k = row;        }
        else if (row <  384) { W = Whh0; K = Hsz; k = row - 128;  }
        else if (row <  640) { W = Wih1; K = Hsz; k = row - 384;  }
        else if (row <  896) { W = Whh1; K = Hsz; k = row - 640;  }
        else if (row < 1152) { W = Wih2; K = Hsz; k = row - 896;  }
        else                 { W = Whh2; K = Hsz; k = row - 1152; }
        const int n = gq * Hsz + jbase + jpq * 2;
        float2 v;
        v.x = __ldg(&W[(size_t)n * K + k]);
        v.y = __ldg(&W[(size_t)(n + 1) * K + k]);
        wsm[(size_t)row * 16 + jpq * 4 + gq] = v;
    }

    // ---- zero h state; bias sums; c regs (tid<256 owns (b2, j2l)) ----
    float bs[3][4];
    float c0 = 0.f, c1 = 0.f, c2 = 0.f;
    if (tid < 256) {
        const int b2  = tid & 31;
        const int j2l = tid >> 5;
        const int b = bbase + b2;
        const int j = jbase + j2l;
#pragma unroll
        for (int l = 0; l < 3; l++) {
            g_hTd[l][0][j][b] = make_float2(0.f, 0.f);
            g_hTd[l][1][j][b] = make_float2(0.f, 0.f);
        }
#pragma unroll
        for (int g = 0; g < 4; g++) {
            bs[0][g] = __ldg(&bih0[g * Hsz + j]) + __ldg(&bhh0[g * Hsz + j]);
            bs[1][g] = __ldg(&bih1[g * Hsz + j]) + __ldg(&bhh1[g * Hsz + j]);
            bs[2][g] = __ldg(&bih2[g * Hsz + j]) + __ldg(&bhh2[g * Hsz + j]);
        }
    } else {
#pragma unroll
        for (int l = 0; l < 3; l++)
#pragma unroll
            for (int g = 0; g < 4; g++) bs[l][g] = 0.f;
    }

    group_sync(bg, gen);

    int p0 = 0, p1 = 0, p2 = 0;
    for (int t = 0; t <= TLAST; t++) {
        // layer 0 — every step. wsm rows [0,384).
        layer_update<16, false>(wsm, slab, gsm, 0,
            g_xTd + (size_t)t * Fsz * Bsz, &g_hTd[0][p0][0][0],
            bs[0], c0, &g_hTd[0][p0 ^ 1][0][0], nullptr, 0, jbase, bbase);
        p0 ^= 1;
        group_sync(bg, gen);

        if ((t & 1) == 0) {
            // layer 1 — every 2nd step. rows [384,896).
            layer_update<32, true>(wsm, slab, gsm, 384,
                &g_hTd[0][p0][0][0], &g_hTd[1][p1][0][0],
                bs[1], c1, &g_hTd[1][p1 ^ 1][0][0], nullptr, 0, jbase, bbase);
            p1 ^= 1;
            if ((t & 3) == 0) {
                group_sync(bg, gen);   // publish h1 for layer 2
                // layer 2 — every 4th step. rows [896,1408).
                layer_update<32, true>(wsm, slab, gsm, 896,
                    &g_hTd[1][p1][0][0], &g_hTd[2][p2][0][0],
                    bs[2], c2, &g_hTd[2][p2 ^ 1][0][0], y, t, jbase, bbase);
                p2 ^= 1;
            }
            // later consumers are separated by the barrier after the next layer-0
        }
    }
}

extern "C" void kernel_launch(void* const* d_in, const int* in_sizes, int n_in,
                              void* d_out, int out_size) {
    const float* x    = (const float*)d_in[0];
    const float* Wih0 = (const float*)d_in[1];
    const float* Whh0 = (const float*)d_in[2];
    const float* bih0 = (const float*)d_in[3];
    const float* bhh0 = (const float*)d_in[4];
    const float* Wih1 = (const float*)d_in[5];
    const float* Whh1 = (const float*)d_in[6];
    const float* bih1 = (const float*)d_in[7];
    const float* bhh1 = (const float*)d_in[8];
    const float* Wih2 = (const float*)d_in[9];
    const float* Whh2 = (const float*)d_in[10];
    const float* bih2 = (const float*)d_in[11];
    const float* bhh2 = (const float*)d_in[12];
    float* y = (float*)d_out;

    transpose_x<<<dim3(Tsz, Fsz / 32, Bsz / 32), dim3(32, 8)>>>(x);

    cudaFuncSetAttribute(drnn_persistent,
                         cudaFuncAttributeMaxDynamicSharedMemorySize, SMEM_TOTAL);
    drnn_persistent<<<128, NTHR, SMEM_TOTAL>>>(
        Wih0, Whh0, bih0, bhh0,
        Wih1, Whh1, bih1, bhh1,
        Wih2, Whh2, bih2, bhh2, y);
}

// round 15
// speedup vs baseline: 2.1424x; 1.0519x over previous
#include <cuda_runtime.h>

#define Bsz 128
#define Tsz 1024
#define Fsz 128
#define Hsz 256
#define TLAST 1020
#define NTHR 512
#define PF 8

typedef unsigned long long ull;

// Persistent state, transposed + duplicated: element [k][b] = (v, v)
__device__ float2 g_hTd[3][2][Hsz][Bsz];
__device__ float2 g_xTd[(size_t)Tsz * Fsz * Bsz];   // [t][f][b] duplicated
__device__ unsigned g_cnt[4][32];
__device__ volatile unsigned g_gen[4][32];

// smem: weights resident (1408 rows x 16 float2 = 128B/row), then slab, then gsm
#define WSM_ROWS 1408
#define SLAB_OFF (WSM_ROWS * 16 * 8)            // 180224
#define GSM_OFF  (SLAB_OFF + 32768)             // 212992
#define SMEM_TOTAL (GSM_OFF + 4096)             // 217088

__device__ __forceinline__ ull ffma2(ull a, ull b, ull c) {
    ull d; asm("fma.rn.f32x2 %0, %1, %2, %3;" : "=l"(d) : "l"(a), "l"(b), "l"(c)); return d;
}
__device__ __forceinline__ ull fadd2(ull a, ull b) {
    ull d; asm("add.rn.f32x2 %0, %1, %2;" : "=l"(d) : "l"(a), "l"(b)); return d;
}
__device__ __forceinline__ float sigf(float x) { return 1.f / (1.f + __expf(-x)); }
__device__ __forceinline__ float tanh_fast(float x) { return fmaf(2.f, sigf(2.f * x), -1.f); }

// x transpose+duplicate: x[B][T][F] -> g_xTd[t][f][b] = (v,v)
__global__ void transpose_x(const float* __restrict__ x) {
    __shared__ float tile[32][33];
    const int t  = blockIdx.x;
    const int f0 = blockIdx.y * 32;
    const int b0 = blockIdx.z * 32;
    const int tx = threadIdx.x, ty = threadIdx.y;
#pragma unroll
    for (int i = 0; i < 4; i++) {
        const int b = b0 + ty * 4 + i;
        tile[ty * 4 + i][tx] = x[(size_t)b * Tsz * Fsz + (size_t)t * Fsz + f0 + tx];
    }
    __syncthreads();
#pragma unroll
    for (int i = 0; i < 4; i++) {
        const int f = f0 + ty * 4 + i;
        const float v = tile[tx][ty * 4 + i];
        g_xTd[(size_t)t * Fsz * Bsz + (size_t)f * Bsz + b0 + tx] = make_float2(v, v);
    }
}

// ---- split 32-block group barrier (arrive / wait) ----
// Every arrive is matched by exactly one later wait in every block, so the
// generation sequence is uniform and the counter-reset ordering is the same
// as the proven fused barrier.
__device__ __forceinline__ void group_arrive(int bg, unsigned &gen) {
    __syncthreads();                 // all this block's prior stores issued
    gen++;                           // uniform across threads
    if (threadIdx.x == 0) {
        __threadfence();             // publish to L2 before signaling
        unsigned old = atomicAdd(&g_cnt[bg][0], 1u);
        if (old == 31u) {
            g_cnt[bg][0] = 0u;
            __threadfence();
            atomicExch((unsigned*)&g_gen[bg][0], gen);
        }
    }
}
__device__ __forceinline__ void group_wait(int bg, unsigned gen) {
    if (threadIdx.x == 0) {
        while (g_gen[bg][0] != gen) { }
        __threadfence();             // acquire
    }
    __syncthreads();
}

// One GEMM segment over NR*8 k-rows: acc += src_rows * W_rows (weights resident
// in wsm at rows [rowbase, rowbase + NR*8)). Identical data path to the proven
// R10 kernel, just segmented.
template<int NR, bool COH>
__device__ __forceinline__ void gemm_seg(
    const float2* __restrict__ wsm, int rowbase,
    const float2* __restrict__ src,
    int bbase, int kh, int bH, int jp, int bo,
    ull acc[8])
{
    const float4* p = (const float4*)(src + (size_t)kh * Bsz + bbase + bH * 16 + bo * 2);
    const float2* wr = wsm + (size_t)(rowbase + kh) * 16 + (jp << 2);

    float4 xbuf[PF];
#pragma unroll
    for (int q = 0; q < PF; q++)
        xbuf[q] = COH ? __ldcg(p + (size_t)q * 4 * Bsz)
                      : __ldg (p + (size_t)q * 4 * Bsz);

#pragma unroll
    for (int r = 0; r < NR; r++) {
        const int q = r % PF;
        const ull x0 = ((const ull*)&xbuf[q])[0];
        const ull x1 = ((const ull*)&xbuf[q])[1];
        const int pf = r + PF;
        if (pf < NR)
            xbuf[q] = COH ? __ldcg(p + (size_t)pf * 4 * Bsz)
                          : __ldg (p + (size_t)pf * 4 * Bsz);
        const ulonglong2 wa = *(const ulonglong2*)(wr + (size_t)r * 128);
        const ulonglong2 wb = *(const ulonglong2*)(wr + (size_t)r * 128 + 2);
        acc[0] = ffma2(wa.x, x0, acc[0]); acc[1] = ffma2(wa.x, x1, acc[1]);
        acc[2] = ffma2(wa.y, x0, acc[2]); acc[3] = ffma2(wa.y, x1, acc[3]);
        acc[4] = ffma2(wb.x, x0, acc[4]); acc[5] = ffma2(wb.x, x1, acc[5]);
        acc[6] = ffma2(wb.y, x0, acc[6]); acc[7] = ffma2(wb.y, x1, acc[7]);
    }
}

// Cross-warp reduce + LSTM cell (verbatim from the passing R10 kernel).
__device__ __forceinline__ void reduce_epi(
    float2* __restrict__ slab, float* __restrict__ gsm,
    ull acc[8],
    const float* bsum, float& creg,
    float2* __restrict__ houtD, float* __restrict__ yout, int t0,
    int jbase, int bbase,
    int kh, int bH, int jp, int bo)
{
    const int tid = threadIdx.x;
    {
        float2* wp = slab + (size_t)kh * 512 + bH * 64 + bo * 4 + jp;
#pragma unroll
        for (int g = 0; g < 4; g++)
#pragma unroll
            for (int u = 0; u < 2; u++)
                *(ull*)(wp + g * 128 + u * 32) = acc[g * 2 + u];
    }
    __syncthreads();
    {
        const int g1  = tid >> 7;
        const int b1  = (tid >> 2) & 31;
        const int jp1 = tid & 3;
        const int bH1 = b1 >> 4, u1 = b1 & 1, bo1 = (b1 >> 1) & 7;
        const float2* sp = slab + g1 * 128 + bH1 * 64 + u1 * 32 + bo1 * 4 + jp1;
        ull sacc = *(const ull*)sp;
#pragma unroll
        for (int k = 1; k < 8; k++) sacc = fadd2(sacc, *(const ull*)(sp + (size_t)k * 512));
        *(ull*)&gsm[((g1 * 32 + b1) * 8) + jp1 * 2] = sacc;
    }
    __syncthreads();

    if (tid < 256) {
        const int b2  = tid & 31;
        const int j2l = tid >> 5;
        const int b = bbase + b2;
        const int j = jbase + j2l;
        const float vi = gsm[(0 * 32 + b2) * 8 + j2l] + bsum[0];
        const float vf = gsm[(1 * 32 + b2) * 8 + j2l] + bsum[1];
        const float vg = gsm[(2 * 32 + b2) * 8 + j2l] + bsum[2];
        const float vo = gsm[(3 * 32 + b2) * 8 + j2l] + bsum[3];
        const float i_ = sigf(vi);
        const float f_ = sigf(vf);
        const float g_ = tanh_fast(vg);
        const float o_ = sigf(vo);
        const float cn = fmaf(f_, creg, i_ * g_);
        const float hn = o_ * tanh_fast(cn);
        creg = cn;
        houtD[(size_t)j * Bsz + b] = make_float2(hn, hn);
        if (yout) {
#pragma unroll
            for (int u = 0; u < 4; u++)
                yout[((size_t)b * Tsz + (t0 + u)) * Hsz + j] = hn;
        }
    }
}

__global__ void __launch_bounds__(NTHR, 1) drnn_persistent(
    const float* __restrict__ Wih0, const float* __restrict__ Whh0,
    const float* __restrict__ bih0, const float* __restrict__ bhh0,
    const float* __restrict__ Wih1, const float* __restrict__ Whh1,
    const float* __restrict__ bih1, const float* __restrict__ bhh1,
    const float* __restrict__ Wih2, const float* __restrict__ Whh2,
    const float* __restrict__ bih2, const float* __restrict__ bhh2,
    float* __restrict__ y)
{
    extern __shared__ char sm[];
    float2* wsm  = (float2*)sm;
    float2* slab = (float2*)(sm + SLAB_OFF);
    float*  gsm  = (float*)(sm + GSM_OFF);

    const int tid = threadIdx.x;
    const int bid = blockIdx.x;
    const int jg = bid >> 2;      // 0..31
    const int bg = bid & 3;       // 0..3
    const int jbase = jg * 8;
    const int bbase = bg * 32;
    const int lane = tid & 31, warp = tid >> 5;
    const int kh = warp & 7, bH = warp >> 3;
    const int jp = lane & 3, bo = lane >> 2;

    unsigned gen = 0;
    if (jg == 0 && tid == 0) g_gen[bg][0] = 0;  // fenced inside first arrive

    // ---- load all weights into resident smem (once) ----
    for (int e = tid; e < WSM_ROWS * 16; e += NTHR) {
        const int row = e >> 4;
        const int q = e & 15;
        const int jpq = q >> 2, gq = q & 3;
        const float* W; int K, k;
        if      (row <  128) { W = Wih0; K = Fsz; k = row;        }
        else if (row <  384) { W = Whh0; K = Hsz; k = row - 128;  }
        else if (row <  640) { W = Wih1; K = Hsz; k = row - 384;  }
        else if (row <  896) { W = Whh1; K = Hsz; k = row - 640;  }
        else if (row < 1152) { W = Wih2; K = Hsz; k = row - 896;  }
        else                 { W = Whh2; K = Hsz; k = row - 1152; }
        const int n = gq * Hsz + jbase + jpq * 2;
        float2 v;
        v.x = __ldg(&W[(size_t)n * K + k]);
        v.y = __ldg(&W[(size_t)(n + 1) * K + k]);
        wsm[(size_t)row * 16 + jpq * 4 + gq] = v;
    }

    // ---- zero h state; bias sums; c regs (tid<256 owns (b2, j2l)) ----
    float bs[3][4];
    float c0 = 0.f, c1 = 0.f, c2 = 0.f;
    if (tid < 256) {
        const int b2  = tid & 31;
        const int j2l = tid >> 5;
        const int b = bbase + b2;
        const int j = jbase + j2l;
#pragma unroll
        for (int l = 0; l < 3; l++) {
            g_hTd[l][0][j][b] = make_float2(0.f, 0.f);
            g_hTd[l][1][j][b] = make_float2(0.f, 0.f);
        }
#pragma unroll
        for (int g = 0; g < 4; g++) {
            bs[0][g] = __ldg(&bih0[g * Hsz + j]) + __ldg(&bhh0[g * Hsz + j]);
            bs[1][g] = __ldg(&bih1[g * Hsz + j]) + __ldg(&bhh1[g * Hsz + j]);
            bs[2][g] = __ldg(&bih2[g * Hsz + j]) + __ldg(&bhh2[g * Hsz + j]);
        }
    } else {
#pragma unroll
        for (int l = 0; l < 3; l++)
#pragma unroll
            for (int g = 0; g < 4; g++) bs[l][g] = 0.f;
    }

    group_arrive(bg, gen);   // init barrier; waited inside L0 at t=0 (even)

    int p0 = 0, p1 = 0, p2 = 0;
    ull acc[8];
    for (int t = 0; t <= TLAST; t++) {
        // ---- layer 0 — every step. Independent segment first: x (rows 0..127).
#pragma unroll
        for (int i = 0; i < 8; i++) acc[i] = 0ull;
        gemm_seg<16, false>(wsm, 0, g_xTd + (size_t)t * Fsz * Bsz,
                            bbase, kh, bH, jp, bo, acc);
        // h0(t-1) needs the latest barrier only when the previous step didn't
        // already wait it (t-1 odd had no L1; t==0 needs the init barrier).
        if ((t & 1) == 0) group_wait(bg, gen);
        gemm_seg<32, true>(wsm, 128, &g_hTd[0][p0][0][0],
                           bbase, kh, bH, jp, bo, acc);
        reduce_epi(slab, gsm, acc, bs[0], c0,
                   &g_hTd[0][p0 ^ 1][0][0], nullptr, 0,
                   jbase, bbase, kh, bH, jp, bo);
        p0 ^= 1;
        group_arrive(bg, gen);   // publish h0(t)

        if ((t & 1) == 0) {
            // ---- layer 1 — every 2nd step. Recurrent segment (old h1) first.
#pragma unroll
            for (int i = 0; i < 8; i++) acc[i] = 0ull;
            gemm_seg<32, true>(wsm, 640, &g_hTd[1][p1][0][0],
                               bbase, kh, bH, jp, bo, acc);
            group_wait(bg, gen);   // h0(t) now visible group-wide
            gemm_seg<32, true>(wsm, 384, &g_hTd[0][p0][0][0],
                               bbase, kh, bH, jp, bo, acc);
            reduce_epi(slab, gsm, acc, bs[1], c1,
                       &g_hTd[1][p1 ^ 1][0][0], nullptr, 0,
                       jbase, bbase, kh, bH, jp, bo);
            p1 ^= 1;

            if ((t & 3) == 0) {
                group_arrive(bg, gen);   // publish h1(t)
                // ---- layer 2 — every 4th step. Recurrent segment first.
#pragma unroll
                for (int i = 0; i < 8; i++) acc[i] = 0ull;
                gemm_seg<32, true>(wsm, 1152, &g_hTd[2][p2][0][0],
                                   bbase, kh, bH, jp, bo, acc);
                group_wait(bg, gen);   // h1(t) visible
                gemm_seg<32, true>(wsm, 896, &g_hTd[1][p1][0][0],
                                   bbase, kh, bH, jp, bo, acc);
                reduce_epi(slab, gsm, acc, bs[2], c2,
                           &g_hTd[2][p2 ^ 1][0][0], y, t,
                           jbase, bbase, kh, bH, jp, bo);
                p2 ^= 1;
                // no arrive here: next L0's arrive covers h2 consumers (t+4)
            }
            // plain L1 (t%4!=0): its h1 consumers are covered by later barriers
        }
    }
}

extern "C" void kernel_launch(void* const* d_in, const int* in_sizes, int n_in,
                              void* d_out, int out_size) {
    const float* x    = (const float*)d_in[0];
    const float* Wih0 = (const float*)d_in[1];
    const float* Whh0 = (const float*)d_in[2];
    const float* bih0 = (const float*)d_in[3];
    const float* bhh0 = (const float*)d_in[4];
    const float* Wih1 = (const float*)d_in[5];
    const float* Whh1 = (const float*)d_in[6];
    const float* bih1 = (const float*)d_in[7];
    const float* bhh1 = (const float*)d_in[8];
    const float* Wih2 = (const float*)d_in[9];
    const float* Whh2 = (const float*)d_in[10];
    const float* bih2 = (const float*)d_in[11];
    const float* bhh2 = (const float*)d_in[12];
    float* y = (float*)d_out;

    transpose_x<<<dim3(Tsz, Fsz / 32, Bsz / 32), dim3(32, 8)>>>(x);

    cudaFuncSetAttribute(drnn_persistent,
                         cudaFuncAttributeMaxDynamicSharedMemorySize, SMEM_TOTAL);
    drnn_persistent<<<128, NTHR, SMEM_TOTAL>>>(
        Wih0, Whh0, bih0, bhh0,
        Wih1, Whh1, bih1, bhh1,
        Wih2, Whh2, bih2, bhh2, y);
}

// round 16
// speedup vs baseline: 2.2557x; 1.0529x over previous
#include <cuda_runtime.h>

#define Bsz 128
#define Tsz 1024
#define Fsz 128
#define Hsz 256
#define TLAST 1020
#define NTHR 512
#define PF 6

typedef unsigned long long ull;

// Persistent state, transposed + duplicated: element [k][b] = (v, v)
__device__ float2 g_hTd[3][2][Hsz][Bsz];
__device__ float2 g_xTd[(size_t)Tsz * Fsz * Bsz];   // [t][f][b] duplicated
__device__ unsigned g_cnt[4][32];
__device__ volatile unsigned g_gen[4][32];

// smem: weights resident (1408 rows x 16 float2 = 128B/row), slab, gsm, bias
#define WSM_ROWS 1408
#define SLAB_OFF (WSM_ROWS * 16 * 8)            // 180224
#define GSM_OFF  (SLAB_OFF + 32768)             // 212992
#define BSM_OFF  (GSM_OFF + 4096)               // 217088
#define SMEM_TOTAL (BSM_OFF + 512)              // 217600

__device__ __forceinline__ ull ffma2(ull a, ull b, ull c) {
    ull d; asm("fma.rn.f32x2 %0, %1, %2, %3;" : "=l"(d) : "l"(a), "l"(b), "l"(c)); return d;
}
__device__ __forceinline__ ull fadd2(ull a, ull b) {
    ull d; asm("add.rn.f32x2 %0, %1, %2;" : "=l"(d) : "l"(a), "l"(b)); return d;
}
__device__ __forceinline__ float sigf(float x) { return 1.f / (1.f + __expf(-x)); }
__device__ __forceinline__ float tanh_fast(float x) { return fmaf(2.f, sigf(2.f * x), -1.f); }

// x transpose+duplicate: x[B][T][F] -> g_xTd[t][f][b] = (v,v)
__global__ void transpose_x(const float* __restrict__ x) {
    __shared__ float tile[32][33];
    const int t  = blockIdx.x;
    const int f0 = blockIdx.y * 32;
    const int b0 = blockIdx.z * 32;
    const int tx = threadIdx.x, ty = threadIdx.y;
#pragma unroll
    for (int i = 0; i < 4; i++) {
        const int b = b0 + ty * 4 + i;
        tile[ty * 4 + i][tx] = x[(size_t)b * Tsz * Fsz + (size_t)t * Fsz + f0 + tx];
    }
    __syncthreads();
#pragma unroll
    for (int i = 0; i < 4; i++) {
        const int f = f0 + ty * 4 + i;
        const float v = tile[tx][ty * 4 + i];
        g_xTd[(size_t)t * Fsz * Bsz + (size_t)f * Bsz + b0 + tx] = make_float2(v, v);
    }
}

// ---- split 32-block group barrier (arrive / wait), proven in R14 ----
__device__ __forceinline__ void group_arrive(int bg, unsigned &gen) {
    __syncthreads();
    gen++;
    if (threadIdx.x == 0) {
        __threadfence();
        unsigned old = atomicAdd(&g_cnt[bg][0], 1u);
        if (old == 31u) {
            g_cnt[bg][0] = 0u;
            __threadfence();
            atomicExch((unsigned*)&g_gen[bg][0], gen);
        }
    }
}
__device__ __forceinline__ void group_wait(int bg, unsigned gen) {
    if (threadIdx.x == 0) {
        while (g_gen[bg][0] != gen) { }
        __threadfence();
    }
    __syncthreads();
}

// One GEMM segment over NR*8 k-rows. Weight operands double-buffered in regs
// (iter r consumes weights loaded at iter r-1 -> no LDS RAW stall).
template<int NR, bool COH>
__device__ __forceinline__ void gemm_seg(
    const float2* __restrict__ wsm, int rowbase,
    const float2* __restrict__ src,
    int bbase, int kh, int bH, int jp, int bo,
    ull acc[8])
{
    const float4* p = (const float4*)(src + (size_t)kh * Bsz + bbase + bH * 16 + bo * 2);
    const float2* wr = wsm + (size_t)(rowbase + kh) * 16 + (jp << 2);

    float4 xbuf[PF];
#pragma unroll
    for (int q = 0; q < PF; q++)
        xbuf[q] = COH ? __ldcg(p + (size_t)q * 4 * Bsz)
                      : __ldg (p + (size_t)q * 4 * Bsz);
    ulonglong2 wa = *(const ulonglong2*)(wr);
    ulonglong2 wb = *(const ulonglong2*)(wr + 2);

#pragma unroll
    for (int r = 0; r < NR; r++) {
        const int q = r % PF;
        const ull x0 = ((const ull*)&xbuf[q])[0];
        const ull x1 = ((const ull*)&xbuf[q])[1];
        const int pf = r + PF;
        if (pf < NR)
            xbuf[q] = COH ? __ldcg(p + (size_t)pf * 4 * Bsz)
                          : __ldg (p + (size_t)pf * 4 * Bsz);
        ulonglong2 wan, wbn;
        if (r + 1 < NR) {
            wan = *(const ulonglong2*)(wr + (size_t)(r + 1) * 128);
            wbn = *(const ulonglong2*)(wr + (size_t)(r + 1) * 128 + 2);
        }
        acc[0] = ffma2(wa.x, x0, acc[0]); acc[1] = ffma2(wa.x, x1, acc[1]);
        acc[2] = ffma2(wa.y, x0, acc[2]); acc[3] = ffma2(wa.y, x1, acc[3]);
        acc[4] = ffma2(wb.x, x0, acc[4]); acc[5] = ffma2(wb.x, x1, acc[5]);
        acc[6] = ffma2(wb.y, x0, acc[6]); acc[7] = ffma2(wb.y, x1, acc[7]);
        if (r + 1 < NR) { wa = wan; wb = wbn; }
    }
}

// Cross-warp reduce + LSTM cell (R10/R14 data path; bias from smem).
__device__ __forceinline__ void reduce_epi(
    float2* __restrict__ slab, float* __restrict__ gsm,
    ull acc[8],
    const float* __restrict__ bsl,   // smem, [g*8 + j2l]
    float& creg,
    float2* __restrict__ houtD, float* __restrict__ yout, int t0,
    int jbase, int bbase,
    int kh, int bH, int jp, int bo)
{
    const int tid = threadIdx.x;
    {
        float2* wp = slab + (size_t)kh * 512 + bH * 64 + bo * 4 + jp;
#pragma unroll
        for (int g = 0; g < 4; g++)
#pragma unroll
            for (int u = 0; u < 2; u++)
                *(ull*)(wp + g * 128 + u * 32) = acc[g * 2 + u];
    }
    __syncthreads();
    {
        const int g1  = tid >> 7;
        const int b1  = (tid >> 2) & 31;
        const int jp1 = tid & 3;
        const int bH1 = b1 >> 4, u1 = b1 & 1, bo1 = (b1 >> 1) & 7;
        const float2* sp = slab + g1 * 128 + bH1 * 64 + u1 * 32 + bo1 * 4 + jp1;
        ull sacc = *(const ull*)sp;
#pragma unroll
        for (int k = 1; k < 8; k++) sacc = fadd2(sacc, *(const ull*)(sp + (size_t)k * 512));
        *(ull*)&gsm[((g1 * 32 + b1) * 8) + jp1 * 2] = sacc;
    }
    __syncthreads();

    if (tid < 256) {
        const int b2  = tid & 31;
        const int j2l = tid >> 5;
        const int b = bbase + b2;
        const int j = jbase + j2l;
        const float vi = gsm[(0 * 32 + b2) * 8 + j2l] + bsl[0 * 8 + j2l];
        const float vf = gsm[(1 * 32 + b2) * 8 + j2l] + bsl[1 * 8 + j2l];
        const float vg = gsm[(2 * 32 + b2) * 8 + j2l] + bsl[2 * 8 + j2l];
        const float vo = gsm[(3 * 32 + b2) * 8 + j2l] + bsl[3 * 8 + j2l];
        const float i_ = sigf(vi);
        const float f_ = sigf(vf);
        const float g_ = tanh_fast(vg);
        const float o_ = sigf(vo);
        const float cn = fmaf(f_, creg, i_ * g_);
        const float hn = o_ * tanh_fast(cn);
        creg = cn;
        houtD[(size_t)j * Bsz + b] = make_float2(hn, hn);
        if (yout) {
#pragma unroll
            for (int u = 0; u < 4; u++)
                yout[((size_t)b * Tsz + (t0 + u)) * Hsz + j] = hn;
        }
    }
}

__global__ void __launch_bounds__(NTHR, 1) drnn_persistent(
    const float* __restrict__ Wih0, const float* __restrict__ Whh0,
    const float* __restrict__ bih0, const float* __restrict__ bhh0,
    const float* __restrict__ Wih1, const float* __restrict__ Whh1,
    const float* __restrict__ bih1, const float* __restrict__ bhh1,
    const float* __restrict__ Wih2, const float* __restrict__ Whh2,
    const float* __restrict__ bih2, const float* __restrict__ bhh2,
    float* __restrict__ y)
{
    extern __shared__ char sm[];
    float2* wsm  = (float2*)sm;
    float2* slab = (float2*)(sm + SLAB_OFF);
    float*  gsm  = (float*)(sm + GSM_OFF);
    float*  bsm  = (float*)(sm + BSM_OFF);   // [3][4][8]

    const int tid = threadIdx.x;
    const int bid = blockIdx.x;
    const int jg = bid >> 2;      // 0..31
    const int bg = bid & 3;       // 0..3
    const int jbase = jg * 8;
    const int bbase = bg * 32;
    const int lane = tid & 31, warp = tid >> 5;
    const int kh = warp & 7, bH = warp >> 3;
    const int jp = lane & 3, bo = lane >> 2;

    unsigned gen = 0;
    if (jg == 0 && tid == 0) g_gen[bg][0] = 0;  // fenced inside first arrive

    // ---- load all weights into resident smem (once) ----
    for (int e = tid; e < WSM_ROWS * 16; e += NTHR) {
        const int row = e >> 4;
        const int q = e & 15;
        const int jpq = q >> 2, gq = q & 3;
        const float* W; int K, k;
        if      (row <  128) { W = Wih0; K = Fsz; k = row;        }
        else if (row <  384) { W = Whh0; K = Hsz; k = row - 128;  }
        else if (row <  640) { W = Wih1; K = Hsz; k = row - 384;  }
        else if (row <  896) { W = Whh1; K = Hsz; k = row - 640;  }
        else if (row < 1152) { W = Wih2; K = Hsz; k = row - 896;  }
        else                 { W = Whh2; K = Hsz; k = row - 1152; }
        const int n = gq * Hsz + jbase + jpq * 2;
        float2 v;
        v.x = __ldg(&W[(size_t)n * K + k]);
        v.y = __ldg(&W[(size_t)(n + 1) * K + k]);
        wsm[(size_t)row * 16 + jpq * 4 + gq] = v;
    }

    // ---- bias sums into smem: bsm[l][g][j2l] ----
    if (tid < 96) {
        const int l = tid >> 5;
        const int g = (tid >> 3) & 3;
        const int j2l = tid & 7;
        const int j = jbase + j2l;
        const float* bi = (l == 0) ? bih0 : (l == 1) ? bih1 : bih2;
        const float* bh = (l == 0) ? bhh0 : (l == 1) ? bhh1 : bhh2;
        bsm[l * 32 + g * 8 + j2l] = __ldg(&bi[g * Hsz + j]) + __ldg(&bh[g * Hsz + j]);
    }

    // ---- zero h state; c regs (tid<256 owns (b2, j2l)) ----
    float c0 = 0.f, c1 = 0.f, c2 = 0.f;
    if (tid < 256) {
        const int b2  = tid & 31;
        const int j2l = tid >> 5;
        const int b = bbase + b2;
        const int j = jbase + j2l;
#pragma unroll
        for (int l = 0; l < 3; l++) {
            g_hTd[l][0][j][b] = make_float2(0.f, 0.f);
            g_hTd[l][1][j][b] = make_float2(0.f, 0.f);
        }
    }

    group_arrive(bg, gen);   // init barrier; waited inside L0 at t=0 (even)

    int p0 = 0, p1 = 0, p2 = 0;
    ull acc[8];
    for (int t = 0; t <= TLAST; t++) {
        // ---- layer 0 — every step. Independent segment first: x (rows 0..127).
#pragma unroll
        for (int i = 0; i < 8; i++) acc[i] = 0ull;
        gemm_seg<16, false>(wsm, 0, g_xTd + (size_t)t * Fsz * Bsz,
                            bbase, kh, bH, jp, bo, acc);
        if ((t & 1) == 0) group_wait(bg, gen);
        gemm_seg<32, true>(wsm, 128, &g_hTd[0][p0][0][0],
                           bbase, kh, bH, jp, bo, acc);
        reduce_epi(slab, gsm, acc, bsm, c0,
                   &g_hTd[0][p0 ^ 1][0][0], nullptr, 0,
                   jbase, bbase, kh, bH, jp, bo);
        p0 ^= 1;
        group_arrive(bg, gen);   // publish h0(t)

        if ((t & 1) == 0) {
            // ---- layer 1 — every 2nd step. Recurrent segment (old h1) first.
#pragma unroll
            for (int i = 0; i < 8; i++) acc[i] = 0ull;
            gemm_seg<32, true>(wsm, 640, &g_hTd[1][p1][0][0],
                               bbase, kh, bH, jp, bo, acc);
            group_wait(bg, gen);   // h0(t) now visible group-wide
            gemm_seg<32, true>(wsm, 384, &g_hTd[0][p0][0][0],
                               bbase, kh, bH, jp, bo, acc);
            reduce_epi(slab, gsm, acc, bsm + 32, c1,
                       &g_hTd[1][p1 ^ 1][0][0], nullptr, 0,
                       jbase, bbase, kh, bH, jp, bo);
            p1 ^= 1;

            if ((t & 3) == 0) {
                group_arrive(bg, gen);   // publish h1(t)
                // ---- layer 2 — every 4th step. Recurrent segment first.
#pragma unroll
                for (int i = 0; i < 8; i++) acc[i] = 0ull;
                gemm_seg<32, true>(wsm, 1152, &g_hTd[2][p2][0][0],
                                   bbase, kh, bH, jp, bo, acc);
                group_wait(bg, gen);   // h1(t) visible
                gemm_seg<32, true>(wsm, 896, &g_hTd[1][p1][0][0],
                                   bbase, kh, bH, jp, bo, acc);
                reduce_epi(slab, gsm, acc, bsm + 64, c2,
                           &g_hTd[2][p2 ^ 1][0][0], y, t,
                           jbase, bbase, kh, bH, jp, bo);
                p2 ^= 1;
                // no arrive here: next L0's arrive covers h2 consumers (t+4)
            }
        }
    }
}

extern "C" void kernel_launch(void* const* d_in, const int* in_sizes, int n_in,
                              void* d_out, int out_size) {
    const float* x    = (const float*)d_in[0];
    const float* Wih0 = (const float*)d_in[1];
    const float* Whh0 = (const float*)d_in[2];
    const float* bih0 = (const float*)d_in[3];
    const float* bhh0 = (const float*)d_in[4];
    const float* Wih1 = (const float*)d_in[5];
    const float* Whh1 = (const float*)d_in[6];
    const float* bih1 = (const float*)d_in[7];
    const float* bhh1 = (const float*)d_in[8];
    const float* Wih2 = (const float*)d_in[9];
    const float* Whh2 = (const float*)d_in[10];
    const float* bih2 = (const float*)d_in[11];
    const float* bhh2 = (const float*)d_in[12];
    float* y = (float*)d_out;

    transpose_x<<<dim3(Tsz, Fsz / 32, Bsz / 32), dim3(32, 8)>>>(x);

    cudaFuncSetAttribute(drnn_persistent,
                         cudaFuncAttributeMaxDynamicSharedMemorySize, SMEM_TOTAL);
    drnn_persistent<<<128, NTHR, SMEM_TOTAL>>>(
        Wih0, Whh0, bih0, bhh0,
        Wih1, Whh1, bih1, bhh1,
        Wih2, Whh2, bih2, bhh2, y);
}

// round 17
// speedup vs baseline: 2.5723x; 1.1403x over previous
#include <cuda_runtime.h>

#define Bsz 128
#define Tsz 1024
#define Fsz 128
#define Hsz 256
#define TLAST 1020
#define NTHR 512
#define PF 8

typedef unsigned long long ull;

// Persistent state, transposed, PLAIN float: element [k][b] = v
__device__ float g_hT[3][2][Hsz][Bsz];
__device__ float g_xT[(size_t)Tsz * Fsz * Bsz];   // [t][f][b]
__device__ unsigned g_cnt[4][32];
__device__ volatile unsigned g_gen[4][32];

// smem: weights resident (1408 rows x 16 float2 = 128B/row), slab, gsm, bias
#define WSM_ROWS 1408
#define SLAB_OFF (WSM_ROWS * 16 * 8)            // 180224
#define GSM_OFF  (SLAB_OFF + 32768)             // 212992
#define BSM_OFF  (GSM_OFF + 4096)               // 217088
#define SMEM_TOTAL (BSM_OFF + 512)              // 217600

__device__ __forceinline__ ull ffma2(ull a, ull b, ull c) {
    ull d; asm("fma.rn.f32x2 %0, %1, %2, %3;" : "=l"(d) : "l"(a), "l"(b), "l"(c)); return d;
}
__device__ __forceinline__ ull fadd2(ull a, ull b) {
    ull d; asm("add.rn.f32x2 %0, %1, %2;" : "=l"(d) : "l"(a), "l"(b)); return d;
}
__device__ __forceinline__ ull dup2(float x) {
    ull d; asm("mov.b64 %0, {%1, %1};" : "=l"(d) : "f"(x)); return d;
}
__device__ __forceinline__ float sigf(float x) { return 1.f / (1.f + __expf(-x)); }
__device__ __forceinline__ float tanh_fast(float x) { return fmaf(2.f, sigf(2.f * x), -1.f); }

// x transpose: x[B][T][F] -> g_xT[t][f][b]
__global__ void transpose_x(const float* __restrict__ x) {
    __shared__ float tile[32][33];
    const int t  = blockIdx.x;
    const int f0 = blockIdx.y * 32;
    const int b0 = blockIdx.z * 32;
    const int tx = threadIdx.x, ty = threadIdx.y;
#pragma unroll
    for (int i = 0; i < 4; i++) {
        const int b = b0 + ty * 4 + i;
        tile[ty * 4 + i][tx] = x[(size_t)b * Tsz * Fsz + (size_t)t * Fsz + f0 + tx];
    }
    __syncthreads();
#pragma unroll
    for (int i = 0; i < 4; i++) {
        const int f = f0 + ty * 4 + i;
        g_xT[(size_t)t * Fsz * Bsz + (size_t)f * Bsz + b0 + tx] = tile[tx][ty * 4 + i];
    }
}

// ---- split 32-block group barrier (arrive / wait), proven in R14/R15 ----
__device__ __forceinline__ void group_arrive(int bg, unsigned &gen) {
    __syncthreads();
    gen++;
    if (threadIdx.x == 0) {
        __threadfence();
        unsigned old = atomicAdd(&g_cnt[bg][0], 1u);
        if (old == 31u) {
            g_cnt[bg][0] = 0u;
            __threadfence();
            atomicExch((unsigned*)&g_gen[bg][0], gen);
        }
    }
}
__device__ __forceinline__ void group_wait(int bg, unsigned gen) {
    if (threadIdx.x == 0) {
        while (g_gen[bg][0] != gen) { }
        __threadfence();
    }
    __syncthreads();
}

// One GEMM segment over NR*8 k-rows. Inputs are PLAIN float rows [k][Bsz];
// each lane loads float2 (2 batch) and duplicates in-register. Weight operands
// double-buffered in regs (no LDS RAW stall on the critical path).
template<int NR, bool COH>
__device__ __forceinline__ void gemm_seg(
    const float2* __restrict__ wsm, int rowbase,
    const float* __restrict__ src,
    int bbase, int kh, int bH, int jp, int bo,
    ull acc[8])
{
    const float2* p = (const float2*)(src + (size_t)kh * Bsz + bbase + bH * 16 + bo * 2);
    const float2* wr = wsm + (size_t)(rowbase + kh) * 16 + (jp << 2);

    float2 xbuf[PF];
#pragma unroll
    for (int q = 0; q < PF; q++)
        xbuf[q] = COH ? __ldcg(p + (size_t)q * 4 * Bsz)
                      : __ldg (p + (size_t)q * 4 * Bsz);
    ulonglong2 wa = *(const ulonglong2*)(wr);
    ulonglong2 wb = *(const ulonglong2*)(wr + 2);

#pragma unroll
    for (int r = 0; r < NR; r++) {
        const int q = r % PF;
        const ull x0 = dup2(xbuf[q].x);
        const ull x1 = dup2(xbuf[q].y);
        const int pf = r + PF;
        if (pf < NR)
            xbuf[q] = COH ? __ldcg(p + (size_t)pf * 4 * Bsz)
                          : __ldg (p + (size_t)pf * 4 * Bsz);
        ulonglong2 wan, wbn;
        if (r + 1 < NR) {
            wan = *(const ulonglong2*)(wr + (size_t)(r + 1) * 128);
            wbn = *(const ulonglong2*)(wr + (size_t)(r + 1) * 128 + 2);
        }
        acc[0] = ffma2(wa.x, x0, acc[0]); acc[1] = ffma2(wa.x, x1, acc[1]);
        acc[2] = ffma2(wa.y, x0, acc[2]); acc[3] = ffma2(wa.y, x1, acc[3]);
        acc[4] = ffma2(wb.x, x0, acc[4]); acc[5] = ffma2(wb.x, x1, acc[5]);
        acc[6] = ffma2(wb.y, x0, acc[6]); acc[7] = ffma2(wb.y, x1, acc[7]);
        if (r + 1 < NR) { wa = wan; wb = wbn; }
    }
}

// Cross-warp reduce + LSTM cell (proven data path; bias from smem).
__device__ __forceinline__ void reduce_epi(
    float2* __restrict__ slab, float* __restrict__ gsm,
    ull acc[8],
    const float* __restrict__ bsl,   // smem, [g*8 + j2l]
    float& creg,
    float* __restrict__ hout, float* __restrict__ yout, int t0,
    int jbase, int bbase,
    int kh, int bH, int jp, int bo)
{
    const int tid = threadIdx.x;
    {
        float2* wp = slab + (size_t)kh * 512 + bH * 64 + bo * 4 + jp;
#pragma unroll
        for (int g = 0; g < 4; g++)
#pragma unroll
            for (int u = 0; u < 2; u++)
                *(ull*)(wp + g * 128 + u * 32) = acc[g * 2 + u];
    }
    __syncthreads();
    {
        const int g1  = tid >> 7;
        const int b1  = (tid >> 2) & 31;
        const int jp1 = tid & 3;
        const int bH1 = b1 >> 4, u1 = b1 & 1, bo1 = (b1 >> 1) & 7;
        const float2* sp = slab + g1 * 128 + bH1 * 64 + u1 * 32 + bo1 * 4 + jp1;
        ull sacc = *(const ull*)sp;
#pragma unroll
        for (int k = 1; k < 8; k++) sacc = fadd2(sacc, *(const ull*)(sp + (size_t)k * 512));
        *(ull*)&gsm[((g1 * 32 + b1) * 8) + jp1 * 2] = sacc;
    }
    __syncthreads();

    if (tid < 256) {
        const int b2  = tid & 31;
        const int j2l = tid >> 5;
        const int b = bbase + b2;
        const int j = jbase + j2l;
        const float vi = gsm[(0 * 32 + b2) * 8 + j2l] + bsl[0 * 8 + j2l];
        const float vf = gsm[(1 * 32 + b2) * 8 + j2l] + bsl[1 * 8 + j2l];
        const float vg = gsm[(2 * 32 + b2) * 8 + j2l] + bsl[2 * 8 + j2l];
        const float vo = gsm[(3 * 32 + b2) * 8 + j2l] + bsl[3 * 8 + j2l];
        const float i_ = sigf(vi);
        const float f_ = sigf(vf);
        const float g_ = tanh_fast(vg);
        const float o_ = sigf(vo);
        const float cn = fmaf(f_, creg, i_ * g_);
        const float hn = o_ * tanh_fast(cn);
        creg = cn;
        hout[(size_t)j * Bsz + b] = hn;
        if (yout) {
#pragma unroll
            for (int u = 0; u < 4; u++)
                yout[((size_t)b * Tsz + (t0 + u)) * Hsz + j] = hn;
        }
    }
}

__global__ void __launch_bounds__(NTHR, 1) drnn_persistent(
    const float* __restrict__ Wih0, const float* __restrict__ Whh0,
    const float* __restrict__ bih0, const float* __restrict__ bhh0,
    const float* __restrict__ Wih1, const float* __restrict__ Whh1,
    const float* __restrict__ bih1, const float* __restrict__ bhh1,
    const float* __restrict__ Wih2, const float* __restrict__ Whh2,
    const float* __restrict__ bih2, const float* __restrict__ bhh2,
    float* __restrict__ y)
{
    extern __shared__ char sm[];
    float2* wsm  = (float2*)sm;
    float2* slab = (float2*)(sm + SLAB_OFF);
    float*  gsm  = (float*)(sm + GSM_OFF);
    float*  bsm  = (float*)(sm + BSM_OFF);   // [3][4][8]

    const int tid = threadIdx.x;
    const int bid = blockIdx.x;
    const int jg = bid >> 2;      // 0..31
    const int bg = bid & 3;       // 0..3
    const int jbase = jg * 8;
    const int bbase = bg * 32;
    const int lane = tid & 31, warp = tid >> 5;
    const int kh = warp & 7, bH = warp >> 3;
    const int jp = lane & 3, bo = lane >> 2;

    unsigned gen = 0;
    if (jg == 0 && tid == 0) g_gen[bg][0] = 0;  // fenced inside first arrive

    // ---- load all weights into resident smem (once) ----
    for (int e = tid; e < WSM_ROWS * 16; e += NTHR) {
        const int row = e >> 4;
        const int q = e & 15;
        const int jpq = q >> 2, gq = q & 3;
        const float* W; int K, k;
        if      (row <  128) { W = Wih0; K = Fsz; k = row;        }
        else if (row <  384) { W = Whh0; K = Hsz; k = row - 128;  }
        else if (row <  640) { W = Wih1; K = Hsz; k = row - 384;  }
        else if (row <  896) { W = Whh1; K = Hsz; k = row - 640;  }
        else if (row < 1152) { W = Wih2; K = Hsz; k = row - 896;  }
        else                 { W = Whh2; K = Hsz; k = row - 1152; }
        const int n = gq * Hsz + jbase + jpq * 2;
        float2 v;
        v.x = __ldg(&W[(size_t)n * K + k]);
        v.y = __ldg(&W[(size_t)(n + 1) * K + k]);
        wsm[(size_t)row * 16 + jpq * 4 + gq] = v;
    }

    // ---- bias sums into smem: bsm[l][g][j2l] ----
    if (tid < 96) {
        const int l = tid >> 5;
        const int g = (tid >> 3) & 3;
        const int j2l = tid & 7;
        const int j = jbase + j2l;
        const float* bi = (l == 0) ? bih0 : (l == 1) ? bih1 : bih2;
        const float* bh = (l == 0) ? bhh0 : (l == 1) ? bhh1 : bhh2;
        bsm[l * 32 + g * 8 + j2l] = __ldg(&bi[g * Hsz + j]) + __ldg(&bh[g * Hsz + j]);
    }

    // ---- zero h state; c regs (tid<256 owns (b2, j2l)) ----
    float c0 = 0.f, c1 = 0.f, c2 = 0.f;
    if (tid < 256) {
        const int b2  = tid & 31;
        const int j2l = tid >> 5;
        const int b = bbase + b2;
        const int j = jbase + j2l;
#pragma unroll
        for (int l = 0; l < 3; l++) {
            g_hT[l][0][j][b] = 0.f;
            g_hT[l][1][j][b] = 0.f;
        }
    }

    group_arrive(bg, gen);   // init barrier; waited inside L0 at t=0 (even)

    int p0 = 0, p1 = 0, p2 = 0;
    ull acc[8];
    for (int t = 0; t <= TLAST; t++) {
        // ---- layer 0 — every step. Independent segment first: x (rows 0..127).
#pragma unroll
        for (int i = 0; i < 8; i++) acc[i] = 0ull;
        gemm_seg<16, false>(wsm, 0, g_xT + (size_t)t * Fsz * Bsz,
                            bbase, kh, bH, jp, bo, acc);
        if ((t & 1) == 0) group_wait(bg, gen);
        gemm_seg<32, true>(wsm, 128, &g_hT[0][p0][0][0],
                           bbase, kh, bH, jp, bo, acc);
        reduce_epi(slab, gsm, acc, bsm, c0,
                   &g_hT[0][p0 ^ 1][0][0], nullptr, 0,
                   jbase, bbase, kh, bH, jp, bo);
        p0 ^= 1;
        group_arrive(bg, gen);   // publish h0(t)

        if ((t & 1) == 0) {
            // ---- layer 1 — every 2nd step. Recurrent segment (old h1) first.
#pragma unroll
            for (int i = 0; i < 8; i++) acc[i] = 0ull;
            gemm_seg<32, true>(wsm, 640, &g_hT[1][p1][0][0],
                               bbase, kh, bH, jp, bo, acc);
            group_wait(bg, gen);   // h0(t) now visible group-wide
            gemm_seg<32, true>(wsm, 384, &g_hT[0][p0][0][0],
                               bbase, kh, bH, jp, bo, acc);
            reduce_epi(slab, gsm, acc, bsm + 32, c1,
                       &g_hT[1][p1 ^ 1][0][0], nullptr, 0,
                       jbase, bbase, kh, bH, jp, bo);
            p1 ^= 1;

            if ((t & 3) == 0) {
                group_arrive(bg, gen);   // publish h1(t)
                // ---- layer 2 — every 4th step. Recurrent segment first.
#pragma unroll
                for (int i = 0; i < 8; i++) acc[i] = 0ull;
                gemm_seg<32, true>(wsm, 1152, &g_hT[2][p2][0][0],
                                   bbase, kh, bH, jp, bo, acc);
                group_wait(bg, gen);   // h1(t) visible
                gemm_seg<32, true>(wsm, 896, &g_hT[1][p1][0][0],
                                   bbase, kh, bH, jp, bo, acc);
                reduce_epi(slab, gsm, acc, bsm + 64, c2,
                           &g_hT[2][p2 ^ 1][0][0], y, t,
                           jbase, bbase, kh, bH, jp, bo);
                p2 ^= 1;
                // no arrive here: next L0's arrive covers h2 consumers (t+4)
            }
        }
    }
}

extern "C" void kernel_launch(void* const* d_in, const int* in_sizes, int n_in,
                              void* d_out, int out_size) {
    const float* x    = (const float*)d_in[0];
    const float* Wih0 = (const float*)d_in[1];
    const float* Whh0 = (const float*)d_in[2];
    const float* bih0 = (const float*)d_in[3];
    const float* bhh0 = (const float*)d_in[4];
    const float* Wih1 = (const float*)d_in[5];
    const float* Whh1 = (const float*)d_in[6];
    const float* bih1 = (const float*)d_in[7];
    const float* bhh1 = (const float*)d_in[8];
    const float* Wih2 = (const float*)d_in[9];
    const float* Whh2 = (const float*)d_in[10];
    const float* bih2 = (const float*)d_in[11];
    const float* bhh2 = (const float*)d_in[12];
    float* y = (float*)d_out;

    transpose_x<<<dim3(Tsz, Fsz / 32, Bsz / 32), dim3(32, 8)>>>(x);

    cudaFuncSetAttribute(drnn_persistent,
                         cudaFuncAttributeMaxDynamicSharedMemorySize, SMEM_TOTAL);
    drnn_persistent<<<128, NTHR, SMEM_TOTAL>>>(
        Wih0, Whh0, bih0, bhh0,
        Wih1, Whh1, bih1, bhh1,
        Wih2, Whh2, bih2, bhh2, y);
}